// round 5
// baseline (speedup 1.0000x reference)
#include <cuda_runtime.h>
#include <cuda_bf16.h>
#include <cstdint>

#define DM   1024
#define NH   16
#define HD   64
#define BSZ  4
#define SEQ  2048
#define MTOT (BSZ * SEQ)   // 8192

// ---------------------------------------------------------------------------
// Scratch (no cudaMalloc allowed)
// ---------------------------------------------------------------------------
__device__ float g_q[BSZ * NH * SEQ * HD];      // [B,H,S,Dh]
__device__ float g_k[BSZ * NH * SEQ * HD];      // [B,H,Dh,S]  (pre-transposed)
__device__ float g_v[BSZ * NH * SEQ * HD];      // [B,H,S,Dh]
__device__ float g_attn[MTOT * DM];             // [B,S,D]
__device__ __nv_bfloat16 g_ah[MTOT * DM];       // activation split hi
__device__ __nv_bfloat16 g_al[MTOT * DM];       // activation split lo
__device__ __nv_bfloat16 g_wh[DM * DM];         // weight split hi
__device__ __nv_bfloat16 g_wl[DM * DM];         // weight split lo

// ---------------------------------------------------------------------------
// Family-portable PTX helpers (NO tcgen05 — harness ptxas targets sm_103)
// ---------------------------------------------------------------------------
__device__ __forceinline__ uint32_t smem_u32(const void* p) {
    uint32_t a;
    asm("{ .reg .u64 t; cvta.to.shared.u64 t, %1; cvt.u32.u64 %0, t; }"
        : "=r"(a) : "l"(p));
    return a;
}
#define SW128(o) ((o) ^ (((o) >> 3) & 0x70))

#define CP_ASYNC16(dst, src) \
    asm volatile("cp.async.cg.shared.global [%0], [%1], 16;" \
                 :: "r"(dst), "l"(src) : "memory")
#define CP_COMMIT() asm volatile("cp.async.commit_group;" ::: "memory")
#define CP_WAIT(n)  asm volatile("cp.async.wait_group %0;" :: "n"(n) : "memory")

#define LDMX4(r0, r1, r2, r3, addr) \
    asm volatile("ldmatrix.sync.aligned.m8n8.x4.shared.b16 {%0,%1,%2,%3}, [%4];" \
                 : "=r"(r0), "=r"(r1), "=r"(r2), "=r"(r3) : "r"(addr))

#define MMA16816(d, a, b0, b1) \
    asm volatile("mma.sync.aligned.m16n8k16.row.col.f32.bf16.bf16.f32 " \
                 "{%0,%1,%2,%3},{%4,%5,%6,%7},{%8,%9},{%0,%1,%2,%3};" \
                 : "+f"((d)[0]), "+f"((d)[1]), "+f"((d)[2]), "+f"((d)[3]) \
                 : "r"((a)[0]), "r"((a)[1]), "r"((a)[2]), "r"((a)[3]), \
                   "r"(b0), "r"(b1))

// ---------------------------------------------------------------------------
// Split fp32 -> bf16 hi/lo pair (x = hi + lo, error ~2^-18 relative)
// ---------------------------------------------------------------------------
__global__ __launch_bounds__(256) void split_bf16(const float* __restrict__ in,
                                                  __nv_bfloat16* __restrict__ hi,
                                                  __nv_bfloat16* __restrict__ lo) {
    const int i = blockIdx.x * blockDim.x + threadIdx.x;   // one float4
    float4 v = ((const float4*)in)[i];
    __nv_bfloat16 hx = __float2bfloat16(v.x);
    __nv_bfloat16 hy = __float2bfloat16(v.y);
    __nv_bfloat16 hz = __float2bfloat16(v.z);
    __nv_bfloat16 hw = __float2bfloat16(v.w);
    __nv_bfloat16 lx = __float2bfloat16(v.x - __bfloat162float(hx));
    __nv_bfloat16 ly = __float2bfloat16(v.y - __bfloat162float(hy));
    __nv_bfloat16 lz = __float2bfloat16(v.z - __bfloat162float(hz));
    __nv_bfloat16 lw = __float2bfloat16(v.w - __bfloat162float(hw));
    ((__nv_bfloat162*)hi)[2 * i]     = __nv_bfloat162(hx, hy);
    ((__nv_bfloat162*)hi)[2 * i + 1] = __nv_bfloat162(hz, hw);
    ((__nv_bfloat162*)lo)[2 * i]     = __nv_bfloat162(lx, ly);
    ((__nv_bfloat162*)lo)[2 * i + 1] = __nv_bfloat162(lz, lw);
}

// ---------------------------------------------------------------------------
// HMMA bf16 x3-split GEMM: C[8192,1024] = (Ah+Al)@(Wh+Wl)^T + bias.
// CTA 128m x 128n, BK=64, 256 thr / 8 warps (each 64x32), cp.async double buf.
// NT layout: W[n][k] k-contiguous == col-major B for mma .row.col (no transposes).
// MODE 0: scatter [B,H,S,Dh]; MODE 1: row-major; MODE 2: [B,H,Dh,S] via smem-T.
// ---------------------------------------------------------------------------
#define GM_BUFSZ 65536                    // Ah 16K | Al 16K | Wh 16K | Wl 16K
#define GM_SMEM  (2 * GM_BUFSZ)           // 131072

template <int MODE>
__global__ __launch_bounds__(256, 1) void gemm_hmma(
    const __nv_bfloat16* __restrict__ Ah, const __nv_bfloat16* __restrict__ Al,
    const __nv_bfloat16* __restrict__ Wh, const __nv_bfloat16* __restrict__ Wl,
    const float* __restrict__ bias, float* __restrict__ C) {
    extern __shared__ __align__(1024) char smem[];
    const int tid = threadIdx.x;
    const int wid = tid >> 5;
    const int l   = tid & 31;
    const int m0  = blockIdx.x * 128;
    const int n0  = blockIdx.y * 128;
    const int wm  = (wid & 1) * 64;        // warp m-offset
    const int wn  = (wid >> 1) * 32;       // warp n-offset
    const uint32_t sb = smem_u32(smem);

    // ---- async tile loader: k-chunk kb -> buffer at smem byte offset boff ----
    auto load_tiles = [&](int kb, uint32_t boff) {
#pragma unroll
        for (int t = 0; t < 4; t++) {                 // 1024 16B-chunks per tile
            const int f   = tid + t * 256;
            const int row = f >> 3, c = f & 7;        // row 0..127, chunk 0..7
            const uint32_t o = SW128(row * 128 + c * 16);
            const size_t sa = (size_t)(m0 + row) * DM + kb * 64 + c * 8;
            const size_t sw = (size_t)(n0 + row) * DM + kb * 64 + c * 8;
            CP_ASYNC16(sb + boff + o,         Ah + sa);
            CP_ASYNC16(sb + boff + 16384 + o, Al + sa);
            CP_ASYNC16(sb + boff + 32768 + o, Wh + sw);
            CP_ASYNC16(sb + boff + 49152 + o, Wl + sw);
        }
    };

    float acc[4][4][4] = {};   // [mt][nt][frag]

    auto compute = [&](uint32_t bu) {
        const uint32_t bAh = bu, bAl = bu + 16384, bWh = bu + 32768, bWl = bu + 49152;
#pragma unroll
        for (int ks = 0; ks < 4; ks++) {
            uint32_t ah[4][4], al[4][4], bh[2][4], bl[2][4];
#pragma unroll
            for (int mt = 0; mt < 4; mt++) {
                const int r = wm + mt * 16 + (l & 15);
                const uint32_t off = SW128((uint32_t)(r * 128 + ks * 32 + (l >> 4) * 16));
                LDMX4(ah[mt][0], ah[mt][1], ah[mt][2], ah[mt][3], bAh + off);
                LDMX4(al[mt][0], al[mt][1], al[mt][2], al[mt][3], bAl + off);
            }
#pragma unroll
            for (int g = 0; g < 2; g++) {
                const int n = wn + g * 16 + (l & 7) + ((l >> 4) << 3);
                const uint32_t off = SW128((uint32_t)(n * 128 + ks * 32 + (((l >> 3) & 1) << 4)));
                LDMX4(bh[g][0], bh[g][1], bh[g][2], bh[g][3], bWh + off);
                LDMX4(bl[g][0], bl[g][1], bl[g][2], bl[g][3], bWl + off);
            }
#pragma unroll
            for (int mt = 0; mt < 4; mt++)
#pragma unroll
                for (int nt = 0; nt < 4; nt++) {
                    const int g = nt >> 1, p = (nt & 1) * 2;
                    MMA16816(acc[mt][nt], ah[mt], bh[g][p], bh[g][p + 1]);
                    MMA16816(acc[mt][nt], ah[mt], bl[g][p], bl[g][p + 1]);
                    MMA16816(acc[mt][nt], al[mt], bh[g][p], bh[g][p + 1]);
                }
        }
    };

    load_tiles(0, 0);
    CP_COMMIT();
    for (int i = 0; i < 16; i++) {
        if (i + 1 < 16) {
            load_tiles(i + 1, ((i + 1) & 1) * GM_BUFSZ);
            CP_COMMIT();
            CP_WAIT(1);
        } else {
            CP_WAIT(0);
        }
        __syncthreads();
        compute(sb + (i & 1) * GM_BUFSZ);
        __syncthreads();
    }

    // ---- epilogue ----
    if (MODE == 2) {
        // per-warp smem transpose -> coalesced stores along s into [B,H,Dh,S]
        float* Tr = (float*)(smem + wid * 8448);   // 32 x (64+1) floats
#pragma unroll
        for (int mt = 0; mt < 4; mt++)
#pragma unroll
            for (int nt = 0; nt < 4; nt++) {
                const int rl = mt * 16 + (l >> 2);
                const int cl = nt * 8 + (l & 3) * 2;
                Tr[cl * 65 + rl]           = acc[mt][nt][0];
                Tr[(cl + 1) * 65 + rl]     = acc[mt][nt][1];
                Tr[cl * 65 + rl + 8]       = acc[mt][nt][2];
                Tr[(cl + 1) * 65 + rl + 8] = acc[mt][nt][3];
            }
        __syncwarp();
        const int b  = m0 >> 11;
        const int s0 = (m0 & (SEQ - 1)) + wm;
#pragma unroll 4
        for (int c = 0; c < 32; c++) {
            const int n_g = n0 + wn + c;
            const int h = n_g >> 6, d = n_g & 63;
            const float bv = __ldg(&bias[n_g]);
            float2 v;
            v.x = Tr[c * 65 + l * 2]     + bv;
            v.y = Tr[c * 65 + l * 2 + 1] + bv;
            *(float2*)&C[((size_t)((b * NH + h) * HD + d)) * SEQ + s0 + l * 2] = v;
        }
    } else {
#pragma unroll
        for (int mt = 0; mt < 4; mt++)
#pragma unroll
            for (int nt = 0; nt < 4; nt++) {
                const int m_g = m0 + wm + mt * 16 + (l >> 2);
                const int n_g = n0 + wn + nt * 8 + (l & 3) * 2;
                const float b0 = __ldg(&bias[n_g]);
                const float b1 = __ldg(&bias[n_g + 1]);
                float2 v0, v1;
                v0.x = acc[mt][nt][0] + b0; v0.y = acc[mt][nt][1] + b1;
                v1.x = acc[mt][nt][2] + b0; v1.y = acc[mt][nt][3] + b1;
                if (MODE == 0) {
                    const int b = m_g >> 11, s = m_g & (SEQ - 1);
                    const int h = n_g >> 6, d = n_g & 63;
                    *(float2*)&C[((size_t)((b * NH + h) * SEQ + s)) * HD + d]     = v0;
                    *(float2*)&C[((size_t)((b * NH + h) * SEQ + s + 8)) * HD + d] = v1;
                } else {
                    *(float2*)&C[(size_t)m_g * DM + n_g]       = v0;
                    *(float2*)&C[(size_t)(m_g + 8) * DM + n_g] = v1;
                }
            }
    }
}

// ---------------------------------------------------------------------------
// Flash attention (unchanged — scalar fp32, conflict-free smem)
// ---------------------------------------------------------------------------
__global__ __launch_bounds__(256) void flash_attn(const float* __restrict__ gq,
                                                  const float* __restrict__ gkt,
                                                  const float* __restrict__ gv,
                                                  float* __restrict__ out) {
    __shared__ float Qt[64 * 64];
    __shared__ float KP[64 * 64];
    __shared__ float Vs[64 * 64];

    const int qt  = blockIdx.x;
    const int bh  = blockIdx.y;
    const int tid = threadIdx.x;
    const int tx  = tid & 15;
    const int ty  = tid >> 4;

    const float* qbase  = gq  + ((size_t)bh * SEQ + qt * 64) * HD;
    const float* ktbase = gkt + (size_t)bh * HD * SEQ;
    const float* vbase  = gv  + (size_t)bh * SEQ * HD;

#pragma unroll
    for (int u = 0; u < 4; u++) {
        const int f = tid + u * 256;
        const int row = f >> 4;
        const int colf = (f & 15) * 4;
        float4 v = *(const float4*)(qbase + (size_t)row * HD + colf);
        Qt[(colf + 0) * 64 + row] = v.x;
        Qt[(colf + 1) * 64 + row] = v.y;
        Qt[(colf + 2) * 64 + row] = v.z;
        Qt[(colf + 3) * 64 + row] = v.w;
    }

    float o[4][4] = {};
    float mi[4]   = {-1e30f, -1e30f, -1e30f, -1e30f};
    float li[4]   = {};

    for (int j0 = 0; j0 < SEQ; j0 += 64) {
        float4 kf[4], vf[4];
#pragma unroll
        for (int u = 0; u < 4; u++) {
            const int f = tid + u * 256;
            const int row = f >> 4;
            const int colf = (f & 15) * 4;
            kf[u] = *(const float4*)(ktbase + (size_t)row * SEQ + j0 + colf);
            vf[u] = *(const float4*)(vbase + (size_t)(j0 + row) * HD + colf);
        }
        __syncthreads();
#pragma unroll
        for (int u = 0; u < 4; u++) {
            const int f = tid + u * 256;
            const int row = f >> 4;
            const int colf = (f & 15) * 4;
            *(float4*)&KP[row * 64 + colf] = kf[u];
            *(float4*)&Vs[row * 64 + colf] = vf[u];
        }
        __syncthreads();

        float s[4][4] = {};
#pragma unroll 8
        for (int d = 0; d < 64; d++) {
            float qa[4], kb[4];
            *(float4*)qa = *(const float4*)&Qt[d * 64 + ty * 4];
            *(float4*)kb = *(const float4*)&KP[d * 64 + tx * 4];
#pragma unroll
            for (int i = 0; i < 4; i++)
#pragma unroll
                for (int j = 0; j < 4; j++)
                    s[i][j] = fmaf(qa[i], kb[j], s[i][j]);
        }

#pragma unroll
        for (int i = 0; i < 4; i++) {
            float rm = -1e30f;
#pragma unroll
            for (int j = 0; j < 4; j++) {
                s[i][j] *= 0.125f;
                rm = fmaxf(rm, s[i][j]);
            }
#pragma unroll
            for (int off = 8; off > 0; off >>= 1)
                rm = fmaxf(rm, __shfl_xor_sync(0xffffffffu, rm, off));
            const float mnew = fmaxf(mi[i], rm);
            const float corr = __expf(mi[i] - mnew);
            float rs = 0.0f;
#pragma unroll
            for (int j = 0; j < 4; j++) {
                s[i][j] = __expf(s[i][j] - mnew);
                rs += s[i][j];
            }
#pragma unroll
            for (int off = 8; off > 0; off >>= 1)
                rs += __shfl_xor_sync(0xffffffffu, rs, off);
            li[i] = li[i] * corr + rs;
            mi[i] = mnew;
#pragma unroll
            for (int j = 0; j < 4; j++) o[i][j] *= corr;
        }

        __syncthreads();
#pragma unroll
        for (int i = 0; i < 4; i++) {
            float4 ps;
            ps.x = s[i][0]; ps.y = s[i][1]; ps.z = s[i][2]; ps.w = s[i][3];
            *(float4*)&KP[(ty * 4 + i) * 64 + tx * 4] = ps;
        }
        __syncthreads();

#pragma unroll 4
        for (int k0 = 0; k0 < 64; k0 += 4) {
            float p[4][4];
#pragma unroll
            for (int i = 0; i < 4; i++)
                *(float4*)p[i] = *(const float4*)&KP[(ty * 4 + i) * 64 + k0];
#pragma unroll
            for (int kk = 0; kk < 4; kk++) {
                float vv[4];
                *(float4*)vv = *(const float4*)&Vs[(k0 + kk) * 64 + tx * 4];
#pragma unroll
                for (int i = 0; i < 4; i++)
#pragma unroll
                    for (int j = 0; j < 4; j++)
                        o[i][j] = fmaf(p[i][kk], vv[j], o[i][j]);
            }
        }
    }

    const int b = bh >> 4;
    const int h = bh & 15;
#pragma unroll
    for (int i = 0; i < 4; i++) {
        const float inv = 1.0f / li[i];
        const int q = qt * 64 + ty * 4 + i;
        float4 v;
        v.x = o[i][0] * inv;
        v.y = o[i][1] * inv;
        v.z = o[i][2] * inv;
        v.w = o[i][3] * inv;
        *(float4*)(out + ((size_t)(b * SEQ + q)) * DM + h * HD + tx * 4) = v;
    }
}

// ---------------------------------------------------------------------------
extern "C" void kernel_launch(void* const* d_in, const int* in_sizes, int n_in,
                              void* d_out, int out_size) {
    (void)in_sizes; (void)n_in; (void)out_size;
    const float* Q  = (const float*)d_in[0];
    const float* K  = (const float*)d_in[1];
    const float* V  = (const float*)d_in[2];
    const float* Wq = (const float*)d_in[3];
    const float* bq = (const float*)d_in[4];
    const float* Wk = (const float*)d_in[5];
    const float* bk = (const float*)d_in[6];
    const float* Wv = (const float*)d_in[7];
    const float* bv = (const float*)d_in[8];
    const float* Wo = (const float*)d_in[9];
    const float* bo = (const float*)d_in[10];

    float *gq, *gk, *gv, *ga;
    __nv_bfloat16 *ah, *al, *wh, *wl;
    cudaGetSymbolAddress((void**)&gq, g_q);
    cudaGetSymbolAddress((void**)&gk, g_k);
    cudaGetSymbolAddress((void**)&gv, g_v);
    cudaGetSymbolAddress((void**)&ga, g_attn);
    cudaGetSymbolAddress((void**)&ah, g_ah);
    cudaGetSymbolAddress((void**)&al, g_al);
    cudaGetSymbolAddress((void**)&wh, g_wh);
    cudaGetSymbolAddress((void**)&wl, g_wl);

    cudaFuncSetAttribute(gemm_hmma<0>, cudaFuncAttributeMaxDynamicSharedMemorySize, GM_SMEM);
    cudaFuncSetAttribute(gemm_hmma<1>, cudaFuncAttributeMaxDynamicSharedMemorySize, GM_SMEM);
    cudaFuncSetAttribute(gemm_hmma<2>, cudaFuncAttributeMaxDynamicSharedMemorySize, GM_SMEM);

    const int ablk = (MTOT * DM / 4) / 256;   // 8192 blocks
    const int wblk = (DM * DM / 4) / 256;     // 1024 blocks
    dim3 ggrid(MTOT / 128, DM / 128);         // (64, 8)

    // Q projection
    split_bf16<<<wblk, 256>>>(Wq, wh, wl);
    split_bf16<<<ablk, 256>>>(Q, ah, al);
    gemm_hmma<0><<<ggrid, 256, GM_SMEM>>>(ah, al, wh, wl, bq, gq);
    // K projection (transposed output)
    split_bf16<<<wblk, 256>>>(Wk, wh, wl);
    split_bf16<<<ablk, 256>>>(K, ah, al);
    gemm_hmma<2><<<ggrid, 256, GM_SMEM>>>(ah, al, wh, wl, bk, gk);
    // V projection
    split_bf16<<<wblk, 256>>>(Wv, wh, wl);
    split_bf16<<<ablk, 256>>>(V, ah, al);
    gemm_hmma<0><<<ggrid, 256, GM_SMEM>>>(ah, al, wh, wl, bv, gv);

    flash_attn<<<dim3(SEQ / 64, BSZ * NH), 256>>>(gq, gk, gv, ga);

    // Output projection
    split_bf16<<<wblk, 256>>>(Wo, wh, wl);
    split_bf16<<<ablk, 256>>>(ga, ah, al);
    gemm_hmma<1><<<ggrid, 256, GM_SMEM>>>(ah, al, wh, wl, bo, (float*)d_out);
}

// round 6
// speedup vs baseline: 1.5764x; 1.5764x over previous
#include <cuda_runtime.h>
#include <cuda_bf16.h>
#include <cstdint>

#define DM   1024
#define NH   16
#define HD   64
#define BSZ  4
#define SEQ  2048
#define MTOT (BSZ * SEQ)   // 8192

// ---------------------------------------------------------------------------
// Scratch (no cudaMalloc allowed)
// ---------------------------------------------------------------------------
__device__ float g_q[BSZ * NH * SEQ * HD];      // [B,H,S,Dh]
__device__ float g_k[BSZ * NH * SEQ * HD];      // [B,H,Dh,S]  (pre-transposed)
__device__ float g_v[BSZ * NH * SEQ * HD];      // [B,H,S,Dh]
__device__ float g_attn[MTOT * DM];             // [B,S,D]
__device__ __nv_bfloat16 g_ah[MTOT * DM];       // activation split hi
__device__ __nv_bfloat16 g_al[MTOT * DM];       // activation split lo
__device__ __nv_bfloat16 g_wh[DM * DM];         // weight split hi
__device__ __nv_bfloat16 g_wl[DM * DM];         // weight split lo

// ---------------------------------------------------------------------------
// Family-portable PTX helpers (NO tcgen05 — harness ptxas targets sm_103)
// ---------------------------------------------------------------------------
__device__ __forceinline__ uint32_t smem_u32(const void* p) {
    uint32_t a;
    asm("{ .reg .u64 t; cvta.to.shared.u64 t, %1; cvt.u32.u64 %0, t; }"
        : "=r"(a) : "l"(p));
    return a;
}
#define SW128(o) ((o) ^ (((o) >> 3) & 0x70))

#define CP_ASYNC16(dst, src) \
    asm volatile("cp.async.cg.shared.global [%0], [%1], 16;" \
                 :: "r"(dst), "l"(src) : "memory")
#define CP_COMMIT() asm volatile("cp.async.commit_group;" ::: "memory")
#define CP_WAIT(n)  asm volatile("cp.async.wait_group %0;" :: "n"(n) : "memory")

#define LDMX4(r0, r1, r2, r3, addr) \
    asm volatile("ldmatrix.sync.aligned.m8n8.x4.shared.b16 {%0,%1,%2,%3}, [%4];" \
                 : "=r"(r0), "=r"(r1), "=r"(r2), "=r"(r3) : "r"(addr))

#define MMA16816(d, a, b0, b1) \
    asm volatile("mma.sync.aligned.m16n8k16.row.col.f32.bf16.bf16.f32 " \
                 "{%0,%1,%2,%3},{%4,%5,%6,%7},{%8,%9},{%0,%1,%2,%3};" \
                 : "+f"((d)[0]), "+f"((d)[1]), "+f"((d)[2]), "+f"((d)[3]) \
                 : "r"((a)[0]), "r"((a)[1]), "r"((a)[2]), "r"((a)[3]), \
                   "r"(b0), "r"(b1))

// ---------------------------------------------------------------------------
// Split fp32 -> bf16 hi/lo pair (x = hi + lo). 4 float4s / thread (MLP=4).
// ---------------------------------------------------------------------------
__global__ __launch_bounds__(256) void split_bf16(const float* __restrict__ in,
                                                  __nv_bfloat16* __restrict__ hi,
                                                  __nv_bfloat16* __restrict__ lo) {
    const int base = blockIdx.x * 1024 + threadIdx.x;
    float4 v[4];
#pragma unroll
    for (int u = 0; u < 4; u++) v[u] = ((const float4*)in)[base + u * 256];
#pragma unroll
    for (int u = 0; u < 4; u++) {
        const int i = base + u * 256;
        __nv_bfloat16 hx = __float2bfloat16(v[u].x);
        __nv_bfloat16 hy = __float2bfloat16(v[u].y);
        __nv_bfloat16 hz = __float2bfloat16(v[u].z);
        __nv_bfloat16 hw = __float2bfloat16(v[u].w);
        __nv_bfloat16 lx = __float2bfloat16(v[u].x - __bfloat162float(hx));
        __nv_bfloat16 ly = __float2bfloat16(v[u].y - __bfloat162float(hy));
        __nv_bfloat16 lz = __float2bfloat16(v[u].z - __bfloat162float(hz));
        __nv_bfloat16 lw = __float2bfloat16(v[u].w - __bfloat162float(hw));
        ((__nv_bfloat162*)hi)[2 * i]     = __nv_bfloat162(hx, hy);
        ((__nv_bfloat162*)hi)[2 * i + 1] = __nv_bfloat162(hz, hw);
        ((__nv_bfloat162*)lo)[2 * i]     = __nv_bfloat162(lx, ly);
        ((__nv_bfloat162*)lo)[2 * i + 1] = __nv_bfloat162(lz, lw);
    }
}

// ---------------------------------------------------------------------------
// HMMA bf16 x3-split GEMM: C[8192,1024] = (Ah+Al)@(Wh+Wl)^T + bias.
// CTA 128m x 128n, BK=64, 512 thr / 16 warps (each 32x32), cp.async double buf.
// Split terms on OUTER loop -> 8 independent MMAs per term (ILP).
// MODE 0: scatter [B,H,S,Dh]; MODE 1: row-major; MODE 2: [B,H,Dh,S] via smem-T.
// ---------------------------------------------------------------------------
#define GM_BUFSZ 65536                    // Ah 16K | Al 16K | Wh 16K | Wl 16K
#define GM_SMEM  (2 * GM_BUFSZ)           // 131072

template <int MODE>
__global__ __launch_bounds__(512, 1) void gemm_hmma(
    const __nv_bfloat16* __restrict__ Ah, const __nv_bfloat16* __restrict__ Al,
    const __nv_bfloat16* __restrict__ Wh, const __nv_bfloat16* __restrict__ Wl,
    const float* __restrict__ bias, float* __restrict__ C) {
    extern __shared__ __align__(1024) char smem[];
    const int tid = threadIdx.x;
    const int wid = tid >> 5;
    const int l   = tid & 31;
    const int m0  = blockIdx.x * 128;
    const int n0  = blockIdx.y * 128;
    const int wm  = (wid & 3) * 32;        // warp m-offset (4 warps down)
    const int wn  = (wid >> 2) * 32;       // warp n-offset (4 warps across)
    const uint32_t sb = smem_u32(smem);

    // ---- async tile loader: k-chunk kb -> buffer at smem byte offset boff ----
    auto load_tiles = [&](int kb, uint32_t boff) {
#pragma unroll
        for (int t = 0; t < 2; t++) {                 // 1024 16B-chunks / tile
            const int f   = tid + t * 512;
            const int row = f >> 3, c = f & 7;        // row 0..127, chunk 0..7
            const uint32_t o = SW128(row * 128 + c * 16);
            const size_t sa = (size_t)(m0 + row) * DM + kb * 64 + c * 8;
            const size_t sw = (size_t)(n0 + row) * DM + kb * 64 + c * 8;
            CP_ASYNC16(sb + boff + o,         Ah + sa);
            CP_ASYNC16(sb + boff + 16384 + o, Al + sa);
            CP_ASYNC16(sb + boff + 32768 + o, Wh + sw);
            CP_ASYNC16(sb + boff + 49152 + o, Wl + sw);
        }
    };

    float acc[2][4][4] = {};   // [mt][nt][frag]

    auto compute = [&](uint32_t bu) {
        const uint32_t bAh = bu, bAl = bu + 16384, bWh = bu + 32768, bWl = bu + 49152;
#pragma unroll
        for (int ks = 0; ks < 4; ks++) {
            uint32_t ah[2][4], al[2][4], bh[2][4], bl[2][4];
#pragma unroll
            for (int mt = 0; mt < 2; mt++) {
                const int r = wm + mt * 16 + (l & 15);
                const uint32_t off = SW128((uint32_t)(r * 128 + ks * 32 + (l >> 4) * 16));
                LDMX4(ah[mt][0], ah[mt][1], ah[mt][2], ah[mt][3], bAh + off);
                LDMX4(al[mt][0], al[mt][1], al[mt][2], al[mt][3], bAl + off);
            }
#pragma unroll
            for (int g = 0; g < 2; g++) {
                const int n = wn + g * 16 + (l & 7) + ((l >> 4) << 3);
                const uint32_t off = SW128((uint32_t)(n * 128 + ks * 32 + (((l >> 3) & 1) << 4)));
                LDMX4(bh[g][0], bh[g][1], bh[g][2], bh[g][3], bWh + off);
                LDMX4(bl[g][0], bl[g][1], bl[g][2], bl[g][3], bWl + off);
            }
            // term 1: Ah*Wh  (8 independent MMAs)
#pragma unroll
            for (int mt = 0; mt < 2; mt++)
#pragma unroll
                for (int nt = 0; nt < 4; nt++) {
                    const int g = nt >> 1, p = (nt & 1) * 2;
                    MMA16816(acc[mt][nt], ah[mt], bh[g][p], bh[g][p + 1]);
                }
            // term 2: Ah*Wl
#pragma unroll
            for (int mt = 0; mt < 2; mt++)
#pragma unroll
                for (int nt = 0; nt < 4; nt++) {
                    const int g = nt >> 1, p = (nt & 1) * 2;
                    MMA16816(acc[mt][nt], ah[mt], bl[g][p], bl[g][p + 1]);
                }
            // term 3: Al*Wh
#pragma unroll
            for (int mt = 0; mt < 2; mt++)
#pragma unroll
                for (int nt = 0; nt < 4; nt++) {
                    const int g = nt >> 1, p = (nt & 1) * 2;
                    MMA16816(acc[mt][nt], al[mt], bh[g][p], bh[g][p + 1]);
                }
        }
    };

    load_tiles(0, 0);
    CP_COMMIT();
    for (int i = 0; i < 16; i++) {
        if (i + 1 < 16) {
            load_tiles(i + 1, ((i + 1) & 1) * GM_BUFSZ);
            CP_COMMIT();
            CP_WAIT(1);
        } else {
            CP_WAIT(0);
        }
        __syncthreads();
        compute(sb + (i & 1) * GM_BUFSZ);
        __syncthreads();
    }

    // ---- epilogue ----
    if (MODE == 2) {
        // per-warp smem transpose -> coalesced stores along s into [B,H,Dh,S]
        float* Tr = (float*)(smem + wid * 4352);   // 32 x 33 floats + pad
#pragma unroll
        for (int mt = 0; mt < 2; mt++)
#pragma unroll
            for (int nt = 0; nt < 4; nt++) {
                const int rl = mt * 16 + (l >> 2);
                const int cl = nt * 8 + (l & 3) * 2;
                Tr[cl * 33 + rl]           = acc[mt][nt][0];
                Tr[(cl + 1) * 33 + rl]     = acc[mt][nt][1];
                Tr[cl * 33 + rl + 8]       = acc[mt][nt][2];
                Tr[(cl + 1) * 33 + rl + 8] = acc[mt][nt][3];
            }
        __syncwarp();
        const int b  = m0 >> 11;
        const int s0 = (m0 & (SEQ - 1)) + wm;
#pragma unroll 4
        for (int c = 0; c < 32; c++) {
            const int n_g = n0 + wn + c;
            const int h = n_g >> 6, d = n_g & 63;
            C[((size_t)((b * NH + h) * HD + d)) * SEQ + s0 + l] =
                Tr[c * 33 + l] + __ldg(&bias[n_g]);
        }
    } else {
#pragma unroll
        for (int mt = 0; mt < 2; mt++)
#pragma unroll
            for (int nt = 0; nt < 4; nt++) {
                const int m_g = m0 + wm + mt * 16 + (l >> 2);
                const int n_g = n0 + wn + nt * 8 + (l & 3) * 2;
                const float b0 = __ldg(&bias[n_g]);
                const float b1 = __ldg(&bias[n_g + 1]);
                float2 v0, v1;
                v0.x = acc[mt][nt][0] + b0; v0.y = acc[mt][nt][1] + b1;
                v1.x = acc[mt][nt][2] + b0; v1.y = acc[mt][nt][3] + b1;
                if (MODE == 0) {
                    const int b = m_g >> 11, s = m_g & (SEQ - 1);
                    const int h = n_g >> 6, d = n_g & 63;
                    *(float2*)&C[((size_t)((b * NH + h) * SEQ + s)) * HD + d]     = v0;
                    *(float2*)&C[((size_t)((b * NH + h) * SEQ + s + 8)) * HD + d] = v1;
                } else {
                    *(float2*)&C[(size_t)m_g * DM + n_g]       = v0;
                    *(float2*)&C[(size_t)(m_g + 8) * DM + n_g] = v1;
                }
            }
    }
}

// ---------------------------------------------------------------------------
// Flash attention (unchanged — scalar fp32, conflict-free smem)
// ---------------------------------------------------------------------------
__global__ __launch_bounds__(256) void flash_attn(const float* __restrict__ gq,
                                                  const float* __restrict__ gkt,
                                                  const float* __restrict__ gv,
                                                  float* __restrict__ out) {
    __shared__ float Qt[64 * 64];
    __shared__ float KP[64 * 64];
    __shared__ float Vs[64 * 64];

    const int qt  = blockIdx.x;
    const int bh  = blockIdx.y;
    const int tid = threadIdx.x;
    const int tx  = tid & 15;
    const int ty  = tid >> 4;

    const float* qbase  = gq  + ((size_t)bh * SEQ + qt * 64) * HD;
    const float* ktbase = gkt + (size_t)bh * HD * SEQ;
    const float* vbase  = gv  + (size_t)bh * SEQ * HD;

#pragma unroll
    for (int u = 0; u < 4; u++) {
        const int f = tid + u * 256;
        const int row = f >> 4;
        const int colf = (f & 15) * 4;
        float4 v = *(const float4*)(qbase + (size_t)row * HD + colf);
        Qt[(colf + 0) * 64 + row] = v.x;
        Qt[(colf + 1) * 64 + row] = v.y;
        Qt[(colf + 2) * 64 + row] = v.z;
        Qt[(colf + 3) * 64 + row] = v.w;
    }

    float o[4][4] = {};
    float mi[4]   = {-1e30f, -1e30f, -1e30f, -1e30f};
    float li[4]   = {};

    for (int j0 = 0; j0 < SEQ; j0 += 64) {
        float4 kf[4], vf[4];
#pragma unroll
        for (int u = 0; u < 4; u++) {
            const int f = tid + u * 256;
            const int row = f >> 4;
            const int colf = (f & 15) * 4;
            kf[u] = *(const float4*)(ktbase + (size_t)row * SEQ + j0 + colf);
            vf[u] = *(const float4*)(vbase + (size_t)(j0 + row) * HD + colf);
        }
        __syncthreads();
#pragma unroll
        for (int u = 0; u < 4; u++) {
            const int f = tid + u * 256;
            const int row = f >> 4;
            const int colf = (f & 15) * 4;
            *(float4*)&KP[row * 64 + colf] = kf[u];
            *(float4*)&Vs[row * 64 + colf] = vf[u];
        }
        __syncthreads();

        float s[4][4] = {};
#pragma unroll 8
        for (int d = 0; d < 64; d++) {
            float qa[4], kb[4];
            *(float4*)qa = *(const float4*)&Qt[d * 64 + ty * 4];
            *(float4*)kb = *(const float4*)&KP[d * 64 + tx * 4];
#pragma unroll
            for (int i = 0; i < 4; i++)
#pragma unroll
                for (int j = 0; j < 4; j++)
                    s[i][j] = fmaf(qa[i], kb[j], s[i][j]);
        }

#pragma unroll
        for (int i = 0; i < 4; i++) {
            float rm = -1e30f;
#pragma unroll
            for (int j = 0; j < 4; j++) {
                s[i][j] *= 0.125f;
                rm = fmaxf(rm, s[i][j]);
            }
#pragma unroll
            for (int off = 8; off > 0; off >>= 1)
                rm = fmaxf(rm, __shfl_xor_sync(0xffffffffu, rm, off));
            const float mnew = fmaxf(mi[i], rm);
            const float corr = __expf(mi[i] - mnew);
            float rs = 0.0f;
#pragma unroll
            for (int j = 0; j < 4; j++) {
                s[i][j] = __expf(s[i][j] - mnew);
                rs += s[i][j];
            }
#pragma unroll
            for (int off = 8; off > 0; off >>= 1)
                rs += __shfl_xor_sync(0xffffffffu, rs, off);
            li[i] = li[i] * corr + rs;
            mi[i] = mnew;
#pragma unroll
            for (int j = 0; j < 4; j++) o[i][j] *= corr;
        }

        __syncthreads();
#pragma unroll
        for (int i = 0; i < 4; i++) {
            float4 ps;
            ps.x = s[i][0]; ps.y = s[i][1]; ps.z = s[i][2]; ps.w = s[i][3];
            *(float4*)&KP[(ty * 4 + i) * 64 + tx * 4] = ps;
        }
        __syncthreads();

#pragma unroll 4
        for (int k0 = 0; k0 < 64; k0 += 4) {
            float p[4][4];
#pragma unroll
            for (int i = 0; i < 4; i++)
                *(float4*)p[i] = *(const float4*)&KP[(ty * 4 + i) * 64 + k0];
#pragma unroll
            for (int kk = 0; kk < 4; kk++) {
                float vv[4];
                *(float4*)vv = *(const float4*)&Vs[(k0 + kk) * 64 + tx * 4];
#pragma unroll
                for (int i = 0; i < 4; i++)
#pragma unroll
                    for (int j = 0; j < 4; j++)
                        o[i][j] = fmaf(p[i][kk], vv[j], o[i][j]);
            }
        }
    }

    const int b = bh >> 4;
    const int h = bh & 15;
#pragma unroll
    for (int i = 0; i < 4; i++) {
        const float inv = 1.0f / li[i];
        const int q = qt * 64 + ty * 4 + i;
        float4 v;
        v.x = o[i][0] * inv;
        v.y = o[i][1] * inv;
        v.z = o[i][2] * inv;
        v.w = o[i][3] * inv;
        *(float4*)(out + ((size_t)(b * SEQ + q)) * DM + h * HD + tx * 4) = v;
    }
}

// ---------------------------------------------------------------------------
extern "C" void kernel_launch(void* const* d_in, const int* in_sizes, int n_in,
                              void* d_out, int out_size) {
    (void)in_sizes; (void)n_in; (void)out_size;
    const float* Q  = (const float*)d_in[0];
    const float* K  = (const float*)d_in[1];
    const float* V  = (const float*)d_in[2];
    const float* Wq = (const float*)d_in[3];
    const float* bq = (const float*)d_in[4];
    const float* Wk = (const float*)d_in[5];
    const float* bk = (const float*)d_in[6];
    const float* Wv = (const float*)d_in[7];
    const float* bv = (const float*)d_in[8];
    const float* Wo = (const float*)d_in[9];
    const float* bo = (const float*)d_in[10];

    float *gq, *gk, *gv, *ga;
    __nv_bfloat16 *ah, *al, *wh, *wl;
    cudaGetSymbolAddress((void**)&gq, g_q);
    cudaGetSymbolAddress((void**)&gk, g_k);
    cudaGetSymbolAddress((void**)&gv, g_v);
    cudaGetSymbolAddress((void**)&ga, g_attn);
    cudaGetSymbolAddress((void**)&ah, g_ah);
    cudaGetSymbolAddress((void**)&al, g_al);
    cudaGetSymbolAddress((void**)&wh, g_wh);
    cudaGetSymbolAddress((void**)&wl, g_wl);

    cudaFuncSetAttribute(gemm_hmma<0>, cudaFuncAttributeMaxDynamicSharedMemorySize, GM_SMEM);
    cudaFuncSetAttribute(gemm_hmma<1>, cudaFuncAttributeMaxDynamicSharedMemorySize, GM_SMEM);
    cudaFuncSetAttribute(gemm_hmma<2>, cudaFuncAttributeMaxDynamicSharedMemorySize, GM_SMEM);

    const int ablk = (MTOT * DM / 4) / 1024;   // 2048 blocks (4 float4/thread)
    const int wblk = (DM * DM / 4) / 1024;     // 256 blocks
    dim3 ggrid(MTOT / 128, DM / 128);          // (64, 8)

    // Q projection
    split_bf16<<<wblk, 256>>>(Wq, wh, wl);
    split_bf16<<<ablk, 256>>>(Q, ah, al);
    gemm_hmma<0><<<ggrid, 512, GM_SMEM>>>(ah, al, wh, wl, bq, gq);
    // K projection (transposed output)
    split_bf16<<<wblk, 256>>>(Wk, wh, wl);
    split_bf16<<<ablk, 256>>>(K, ah, al);
    gemm_hmma<2><<<ggrid, 512, GM_SMEM>>>(ah, al, wh, wl, bk, gk);
    // V projection
    split_bf16<<<wblk, 256>>>(Wv, wh, wl);
    split_bf16<<<ablk, 256>>>(V, ah, al);
    gemm_hmma<0><<<ggrid, 512, GM_SMEM>>>(ah, al, wh, wl, bv, gv);

    flash_attn<<<dim3(SEQ / 64, BSZ * NH), 256>>>(gq, gk, gv, ga);

    // Output projection
    split_bf16<<<wblk, 256>>>(Wo, wh, wl);
    split_bf16<<<ablk, 256>>>(ga, ah, al);
    gemm_hmma<1><<<ggrid, 512, GM_SMEM>>>(ah, al, wh, wl, bo, (float*)d_out);
}

// round 9
// speedup vs baseline: 3.0591x; 1.9406x over previous
#include <cuda_runtime.h>
#include <cuda_bf16.h>
#include <cstdint>

#define DM   1024
#define NH   16
#define HD   64
#define BSZ  4
#define SEQ  2048
#define MTOT (BSZ * SEQ)   // 8192

// ---------------------------------------------------------------------------
// Scratch (no cudaMalloc allowed) — all bf16 hi/lo pairs
// ---------------------------------------------------------------------------
__device__ __nv_bfloat16 g_qh[BSZ * NH * SEQ * HD];   // [B,H,S,Dh]
__device__ __nv_bfloat16 g_ql[BSZ * NH * SEQ * HD];
__device__ __nv_bfloat16 g_kh[BSZ * NH * SEQ * HD];   // [B,H,S,Dh]
__device__ __nv_bfloat16 g_kl[BSZ * NH * SEQ * HD];
__device__ __nv_bfloat16 g_vh[BSZ * NH * SEQ * HD];   // [B,H,Dh,S] (V^T)
__device__ __nv_bfloat16 g_vl[BSZ * NH * SEQ * HD];
__device__ __nv_bfloat16 g_ah[MTOT * DM];             // activation hi
__device__ __nv_bfloat16 g_al[MTOT * DM];             // activation lo
__device__ __nv_bfloat16 g_wh[DM * DM];               // weight hi
__device__ __nv_bfloat16 g_wl[DM * DM];               // weight lo

// ---------------------------------------------------------------------------
// Family-portable PTX helpers (NO tcgen05 — harness ptxas targets sm_103)
// ---------------------------------------------------------------------------
__device__ __forceinline__ uint32_t smem_u32(const void* p) {
    uint32_t a;
    asm("{ .reg .u64 t; cvta.to.shared.u64 t, %1; cvt.u32.u64 %0, t; }"
        : "=r"(a) : "l"(p));
    return a;
}
#define SW128(o) ((o) ^ (((o) >> 3) & 0x70))

#define CP_ASYNC16(dst, src) \
    asm volatile("cp.async.cg.shared.global [%0], [%1], 16;" \
                 :: "r"(dst), "l"(src) : "memory")
#define CP_COMMIT() asm volatile("cp.async.commit_group;" ::: "memory")
#define CP_WAIT(n)  asm volatile("cp.async.wait_group %0;" :: "n"(n) : "memory")

#define LDMX4(r0, r1, r2, r3, addr) \
    asm volatile("ldmatrix.sync.aligned.m8n8.x4.shared.b16 {%0,%1,%2,%3}, [%4];" \
                 : "=r"(r0), "=r"(r1), "=r"(r2), "=r"(r3) : "r"(addr))

#define MMA16816(d, a, b0, b1) \
    asm volatile("mma.sync.aligned.m16n8k16.row.col.f32.bf16.bf16.f32 " \
                 "{%0,%1,%2,%3},{%4,%5,%6,%7},{%8,%9},{%0,%1,%2,%3};" \
                 : "+f"((d)[0]), "+f"((d)[1]), "+f"((d)[2]), "+f"((d)[3]) \
                 : "r"((a)[0]), "r"((a)[1]), "r"((a)[2]), "r"((a)[3]), \
                   "r"(b0), "r"(b1))

__device__ __forceinline__ uint32_t packbf(float lo, float hi) {
    __nv_bfloat162 t = __floats2bfloat162_rn(lo, hi);
    return *(uint32_t*)&t;
}
__device__ __forceinline__ void split2(float x, __nv_bfloat16& h, __nv_bfloat16& l) {
    h = __float2bfloat16(x);
    l = __float2bfloat16(x - __bfloat162float(h));
}

// ---------------------------------------------------------------------------
// Split fp32 -> bf16 hi/lo pair. 4 float4s / thread (MLP=4).
// ---------------------------------------------------------------------------
__global__ __launch_bounds__(256) void split_bf16(const float* __restrict__ in,
                                                  __nv_bfloat16* __restrict__ hi,
                                                  __nv_bfloat16* __restrict__ lo) {
    const int base = blockIdx.x * 1024 + threadIdx.x;
    float4 v[4];
#pragma unroll
    for (int u = 0; u < 4; u++) v[u] = ((const float4*)in)[base + u * 256];
#pragma unroll
    for (int u = 0; u < 4; u++) {
        const int i = base + u * 256;
        __nv_bfloat16 hx, hy, hz, hw, lx, ly, lz, lw;
        split2(v[u].x, hx, lx); split2(v[u].y, hy, ly);
        split2(v[u].z, hz, lz); split2(v[u].w, hw, lw);
        ((__nv_bfloat162*)hi)[2 * i]     = __nv_bfloat162(hx, hy);
        ((__nv_bfloat162*)hi)[2 * i + 1] = __nv_bfloat162(hz, hw);
        ((__nv_bfloat162*)lo)[2 * i]     = __nv_bfloat162(lx, ly);
        ((__nv_bfloat162*)lo)[2 * i + 1] = __nv_bfloat162(lz, lw);
    }
}

// ---------------------------------------------------------------------------
// HMMA bf16 x3-split GEMM: C[8192,1024] = (Ah+Al)@(Wh+Wl)^T + bias.
// CTA 128m x 128n, BK=64, 512 thr / 16 warps (each 32x32), cp.async double buf.
// MODE 0: bf16 hi/lo out, scattered [B,H,S,Dh]
// MODE 1: fp32 out, row-major [MTOT,DM]
// MODE 2: bf16 hi/lo out, transposed [B,H,Dh,S]
// ---------------------------------------------------------------------------
#define GM_BUFSZ 65536
#define GM_SMEM  (2 * GM_BUFSZ)           // 131072

template <int MODE>
__global__ __launch_bounds__(512, 1) void gemm_hmma(
    const __nv_bfloat16* __restrict__ Ah, const __nv_bfloat16* __restrict__ Al,
    const __nv_bfloat16* __restrict__ Wh, const __nv_bfloat16* __restrict__ Wl,
    const float* __restrict__ bias,
    __nv_bfloat16* __restrict__ Chi, __nv_bfloat16* __restrict__ Clo,
    float* __restrict__ Cf) {
    extern __shared__ __align__(1024) char smem[];
    const int tid = threadIdx.x;
    const int wid = tid >> 5;
    const int l   = tid & 31;
    const int m0  = blockIdx.x * 128;
    const int n0  = blockIdx.y * 128;
    const int wm  = (wid & 3) * 32;
    const int wn  = (wid >> 2) * 32;
    const uint32_t sb = smem_u32(smem);

    auto load_tiles = [&](int kb, uint32_t boff) {
#pragma unroll
        for (int t = 0; t < 2; t++) {
            const int f   = tid + t * 512;
            const int row = f >> 3, c = f & 7;
            const uint32_t o = SW128(row * 128 + c * 16);
            const size_t sa = (size_t)(m0 + row) * DM + kb * 64 + c * 8;
            const size_t sw = (size_t)(n0 + row) * DM + kb * 64 + c * 8;
            CP_ASYNC16(sb + boff + o,         Ah + sa);
            CP_ASYNC16(sb + boff + 16384 + o, Al + sa);
            CP_ASYNC16(sb + boff + 32768 + o, Wh + sw);
            CP_ASYNC16(sb + boff + 49152 + o, Wl + sw);
        }
    };

    float acc[2][4][4] = {};

    auto compute = [&](uint32_t bu) {
        const uint32_t bAh = bu, bAl = bu + 16384, bWh = bu + 32768, bWl = bu + 49152;
#pragma unroll
        for (int ks = 0; ks < 4; ks++) {
            uint32_t ah[2][4], al[2][4], bh[2][4], bl[2][4];
#pragma unroll
            for (int mt = 0; mt < 2; mt++) {
                const int r = wm + mt * 16 + (l & 15);
                const uint32_t off = SW128((uint32_t)(r * 128 + ks * 32 + (l >> 4) * 16));
                LDMX4(ah[mt][0], ah[mt][1], ah[mt][2], ah[mt][3], bAh + off);
                LDMX4(al[mt][0], al[mt][1], al[mt][2], al[mt][3], bAl + off);
            }
#pragma unroll
            for (int g = 0; g < 2; g++) {
                const int n = wn + g * 16 + (l & 7) + ((l >> 4) << 3);
                const uint32_t off = SW128((uint32_t)(n * 128 + ks * 32 + (((l >> 3) & 1) << 4)));
                LDMX4(bh[g][0], bh[g][1], bh[g][2], bh[g][3], bWh + off);
                LDMX4(bl[g][0], bl[g][1], bl[g][2], bl[g][3], bWl + off);
            }
#pragma unroll
            for (int mt = 0; mt < 2; mt++)
#pragma unroll
                for (int nt = 0; nt < 4; nt++) {
                    const int g = nt >> 1, p = (nt & 1) * 2;
                    MMA16816(acc[mt][nt], ah[mt], bh[g][p], bh[g][p + 1]);
                }
#pragma unroll
            for (int mt = 0; mt < 2; mt++)
#pragma unroll
                for (int nt = 0; nt < 4; nt++) {
                    const int g = nt >> 1, p = (nt & 1) * 2;
                    MMA16816(acc[mt][nt], ah[mt], bl[g][p], bl[g][p + 1]);
                }
#pragma unroll
            for (int mt = 0; mt < 2; mt++)
#pragma unroll
                for (int nt = 0; nt < 4; nt++) {
                    const int g = nt >> 1, p = (nt & 1) * 2;
                    MMA16816(acc[mt][nt], al[mt], bh[g][p], bh[g][p + 1]);
                }
        }
    };

    load_tiles(0, 0);
    CP_COMMIT();
    for (int i = 0; i < 16; i++) {
        if (i + 1 < 16) {
            load_tiles(i + 1, ((i + 1) & 1) * GM_BUFSZ);
            CP_COMMIT();
            CP_WAIT(1);
        } else {
            CP_WAIT(0);
        }
        __syncthreads();
        compute(sb + (i & 1) * GM_BUFSZ);
        __syncthreads();
    }

    if (MODE == 2) {
        float* Tr = (float*)(smem + wid * 4352);   // 32 x 33 floats
#pragma unroll
        for (int mt = 0; mt < 2; mt++)
#pragma unroll
            for (int nt = 0; nt < 4; nt++) {
                const int rl = mt * 16 + (l >> 2);
                const int cl = nt * 8 + (l & 3) * 2;
                Tr[cl * 33 + rl]           = acc[mt][nt][0];
                Tr[(cl + 1) * 33 + rl]     = acc[mt][nt][1];
                Tr[cl * 33 + rl + 8]       = acc[mt][nt][2];
                Tr[(cl + 1) * 33 + rl + 8] = acc[mt][nt][3];
            }
        __syncwarp();
        const int b  = m0 >> 11;
        const int s0 = (m0 & (SEQ - 1)) + wm;
#pragma unroll 4
        for (int c = 0; c < 32; c++) {
            const int n_g = n0 + wn + c;
            const int h = n_g >> 6, d = n_g & 63;
            const float x = Tr[c * 33 + l] + __ldg(&bias[n_g]);
            __nv_bfloat16 hh, ll;
            split2(x, hh, ll);
            const size_t idx = ((size_t)((b * NH + h) * HD + d)) * SEQ + s0 + l;
            Chi[idx] = hh;
            Clo[idx] = ll;
        }
    } else {
#pragma unroll
        for (int mt = 0; mt < 2; mt++)
#pragma unroll
            for (int nt = 0; nt < 4; nt++) {
                const int m_g = m0 + wm + mt * 16 + (l >> 2);
                const int n_g = n0 + wn + nt * 8 + (l & 3) * 2;
                const float b0 = __ldg(&bias[n_g]);
                const float b1 = __ldg(&bias[n_g + 1]);
                float x00 = acc[mt][nt][0] + b0, x01 = acc[mt][nt][1] + b1;
                float x10 = acc[mt][nt][2] + b0, x11 = acc[mt][nt][3] + b1;
                if (MODE == 0) {
                    const int b = m_g >> 11, s = m_g & (SEQ - 1);
                    const int h = n_g >> 6, d = n_g & 63;
                    const size_t i0 = ((size_t)((b * NH + h) * SEQ + s)) * HD + d;
                    const size_t i1 = ((size_t)((b * NH + h) * SEQ + s + 8)) * HD + d;
                    __nv_bfloat16 h00, l00, h01, l01, h10, l10, h11, l11;
                    split2(x00, h00, l00); split2(x01, h01, l01);
                    split2(x10, h10, l10); split2(x11, h11, l11);
                    *(__nv_bfloat162*)&Chi[i0] = __nv_bfloat162(h00, h01);
                    *(__nv_bfloat162*)&Clo[i0] = __nv_bfloat162(l00, l01);
                    *(__nv_bfloat162*)&Chi[i1] = __nv_bfloat162(h10, h11);
                    *(__nv_bfloat162*)&Clo[i1] = __nv_bfloat162(l10, l11);
                } else {
                    float2 v0, v1;
                    v0.x = x00; v0.y = x01;
                    v1.x = x10; v1.y = x11;
                    *(float2*)&Cf[(size_t)m_g * DM + n_g]       = v0;
                    *(float2*)&Cf[(size_t)(m_g + 8) * DM + n_g] = v1;
                }
            }
    }
}

// ---------------------------------------------------------------------------
// HMMA flash attention. CTA: 128 q-rows x one (b,h). 256 thr / 8 warps,
// warp = 16 q-rows. Key blocks of 64, cp.async double-buffered K/V hi/lo.
// Scores/PV via bf16 x3-split MMA; P repacked in-register from S accums.
// Output written as bf16 hi/lo into [B,S,DM] activation buffers.
// ---------------------------------------------------------------------------
#define FA_SMEM (32768 + 2 * 32768)    // Q hi/lo 32K | 2 x (Kh,Kl,Vh,Vl 32K)

__global__ __launch_bounds__(256) void flash_hmma(
    const __nv_bfloat16* __restrict__ qh_g, const __nv_bfloat16* __restrict__ ql_g,
    const __nv_bfloat16* __restrict__ kh_g, const __nv_bfloat16* __restrict__ kl_g,
    const __nv_bfloat16* __restrict__ vh_g, const __nv_bfloat16* __restrict__ vl_g,
    __nv_bfloat16* __restrict__ oh_g, __nv_bfloat16* __restrict__ ol_g) {
    extern __shared__ __align__(1024) char smem[];
    const int tid = threadIdx.x;
    const int wid = tid >> 5;
    const int l   = tid & 31;
    const int q0  = blockIdx.x * 128;
    const int bh  = blockIdx.y;
    const int wq  = wid * 16;
    const uint32_t sb  = smem_u32(smem);
    const uint32_t sQh = sb, sQl = sb + 16384;

    // Q tiles (both halves), 4 chunks/thread each
    {
        const __nv_bfloat16* qh_s = qh_g + ((size_t)bh * SEQ + q0) * HD;
        const __nv_bfloat16* ql_s = ql_g + ((size_t)bh * SEQ + q0) * HD;
#pragma unroll
        for (int t = 0; t < 4; t++) {
            const int f = tid + t * 256;
            const int row = f >> 3, c = f & 7;
            const uint32_t o = SW128(row * 128 + c * 16);
            CP_ASYNC16(sQh + o, qh_s + row * HD + c * 8);
            CP_ASYNC16(sQl + o, ql_s + row * HD + c * 8);
        }
    }

    const __nv_bfloat16* kh_s = kh_g + (size_t)bh * SEQ * HD;
    const __nv_bfloat16* kl_s = kl_g + (size_t)bh * SEQ * HD;
    const __nv_bfloat16* vh_s = vh_g + (size_t)bh * HD * SEQ;   // [d][s]
    const __nv_bfloat16* vl_s = vl_g + (size_t)bh * HD * SEQ;

    auto load_kv = [&](int j, uint32_t boff) {
        const int j0 = j * 64;
#pragma unroll
        for (int t = 0; t < 2; t++) {
            const int f = tid + t * 256;
            const int row = f >> 3, c = f & 7;    // row 0..63
            const uint32_t o = SW128(row * 128 + c * 16);
            CP_ASYNC16(sb + boff + o,         kh_s + (size_t)(j0 + row) * HD + c * 8);
            CP_ASYNC16(sb + boff + 8192 + o,  kl_s + (size_t)(j0 + row) * HD + c * 8);
            CP_ASYNC16(sb + boff + 16384 + o, vh_s + (size_t)row * SEQ + j0 + c * 8);
            CP_ASYNC16(sb + boff + 24576 + o, vl_s + (size_t)row * SEQ + j0 + c * 8);
        }
    };

    float oacc[8][4] = {};
    float mi0 = -1e30f, mi1 = -1e30f, li0 = 0.0f, li1 = 0.0f;

    load_kv(0, 32768);
    CP_COMMIT();

    for (int j = 0; j < SEQ / 64; j++) {
        if (j + 1 < SEQ / 64) {
            load_kv(j + 1, 32768u + ((j + 1) & 1) * 32768u);
            CP_COMMIT();
            CP_WAIT(1);
        } else {
            CP_WAIT(0);
        }
        __syncthreads();

        const uint32_t bu  = sb + 32768u + (j & 1) * 32768u;
        const uint32_t bKh = bu, bKl = bu + 8192, bVh = bu + 16384, bVl = bu + 24576;

        // ---- scores S = Q K^T (x3 split) ----
        float sacc[8][4] = {};
#pragma unroll
        for (int ks = 0; ks < 4; ks++) {
            uint32_t qhf[4], qlf[4], khf[4][4], klf[4][4];
            {
                const int r = wq + (l & 15);
                const uint32_t off = SW128((uint32_t)(r * 128 + ks * 32 + (l >> 4) * 16));
                LDMX4(qhf[0], qhf[1], qhf[2], qhf[3], sQh + off);
                LDMX4(qlf[0], qlf[1], qlf[2], qlf[3], sQl + off);
            }
#pragma unroll
            for (int g = 0; g < 4; g++) {
                const int n = g * 16 + (l & 7) + ((l >> 4) << 3);
                const uint32_t off = SW128((uint32_t)(n * 128 + ks * 32 + (((l >> 3) & 1) << 4)));
                LDMX4(khf[g][0], khf[g][1], khf[g][2], khf[g][3], bKh + off);
                LDMX4(klf[g][0], klf[g][1], klf[g][2], klf[g][3], bKl + off);
            }
#pragma unroll
            for (int g = 0; g < 4; g++) {
                MMA16816(sacc[2 * g],     qhf, khf[g][0], khf[g][1]);
                MMA16816(sacc[2 * g + 1], qhf, khf[g][2], khf[g][3]);
            }
#pragma unroll
            for (int g = 0; g < 4; g++) {
                MMA16816(sacc[2 * g],     qhf, klf[g][0], klf[g][1]);
                MMA16816(sacc[2 * g + 1], qhf, klf[g][2], klf[g][3]);
            }
#pragma unroll
            for (int g = 0; g < 4; g++) {
                MMA16816(sacc[2 * g],     qlf, khf[g][0], khf[g][1]);
                MMA16816(sacc[2 * g + 1], qlf, khf[g][2], khf[g][3]);
            }
        }

        // ---- online softmax (rows live in lane quads) ----
        float rm0 = -1e30f, rm1 = -1e30f;
#pragma unroll
        for (int t = 0; t < 8; t++) {
#pragma unroll
            for (int e = 0; e < 4; e++) sacc[t][e] *= 0.125f;
            rm0 = fmaxf(rm0, fmaxf(sacc[t][0], sacc[t][1]));
            rm1 = fmaxf(rm1, fmaxf(sacc[t][2], sacc[t][3]));
        }
        rm0 = fmaxf(rm0, __shfl_xor_sync(0xffffffffu, rm0, 1));
        rm0 = fmaxf(rm0, __shfl_xor_sync(0xffffffffu, rm0, 2));
        rm1 = fmaxf(rm1, __shfl_xor_sync(0xffffffffu, rm1, 1));
        rm1 = fmaxf(rm1, __shfl_xor_sync(0xffffffffu, rm1, 2));
        const float mn0 = fmaxf(mi0, rm0), mn1 = fmaxf(mi1, rm1);
        const float cr0 = __expf(mi0 - mn0), cr1 = __expf(mi1 - mn1);
        float rs0 = 0.0f, rs1 = 0.0f;
#pragma unroll
        for (int t = 0; t < 8; t++) {
            sacc[t][0] = __expf(sacc[t][0] - mn0);
            sacc[t][1] = __expf(sacc[t][1] - mn0);
            sacc[t][2] = __expf(sacc[t][2] - mn1);
            sacc[t][3] = __expf(sacc[t][3] - mn1);
            rs0 += sacc[t][0] + sacc[t][1];
            rs1 += sacc[t][2] + sacc[t][3];
        }
        rs0 += __shfl_xor_sync(0xffffffffu, rs0, 1);
        rs0 += __shfl_xor_sync(0xffffffffu, rs0, 2);
        rs1 += __shfl_xor_sync(0xffffffffu, rs1, 1);
        rs1 += __shfl_xor_sync(0xffffffffu, rs1, 2);
        li0 = li0 * cr0 + rs0;  mi0 = mn0;
        li1 = li1 * cr1 + rs1;  mi1 = mn1;
#pragma unroll
        for (int t = 0; t < 8; t++) {
            oacc[t][0] *= cr0; oacc[t][1] *= cr0;
            oacc[t][2] *= cr1; oacc[t][3] *= cr1;
        }

        // ---- pack P into A-fragments (hi/lo split), in-register ----
        uint32_t ph[4][4], pl[4][4];
#pragma unroll
        for (int kc = 0; kc < 4; kc++) {
#pragma unroll
            for (int half = 0; half < 2; half++) {        // n-tile 2kc+half
                const int t = 2 * kc + half;
                __nv_bfloat16 h0, l0, h1, l1, h2, l2, h3, l3;
                split2(sacc[t][0], h0, l0); split2(sacc[t][1], h1, l1);
                split2(sacc[t][2], h2, l2); split2(sacc[t][3], h3, l3);
                ph[kc][half * 2]     = packbf(__bfloat162float(h0), __bfloat162float(h1));
                ph[kc][half * 2 + 1] = packbf(__bfloat162float(h2), __bfloat162float(h3));
                pl[kc][half * 2]     = packbf(__bfloat162float(l0), __bfloat162float(l1));
                pl[kc][half * 2 + 1] = packbf(__bfloat162float(l2), __bfloat162float(l3));
            }
        }

        // ---- O += P V (x3 split) ----
#pragma unroll
        for (int kc = 0; kc < 4; kc++) {
            uint32_t vhf[4][4], vlf[4][4];
#pragma unroll
            for (int g = 0; g < 4; g++) {
                const int n = g * 16 + (l & 7) + ((l >> 4) << 3);   // n = d
                const uint32_t off = SW128((uint32_t)(n * 128 + kc * 32 + (((l >> 3) & 1) << 4)));
                LDMX4(vhf[g][0], vhf[g][1], vhf[g][2], vhf[g][3], bVh + off);
                LDMX4(vlf[g][0], vlf[g][1], vlf[g][2], vlf[g][3], bVl + off);
            }
#pragma unroll
            for (int g = 0; g < 4; g++) {
                MMA16816(oacc[2 * g],     ph[kc], vhf[g][0], vhf[g][1]);
                MMA16816(oacc[2 * g + 1], ph[kc], vhf[g][2], vhf[g][3]);
            }
#pragma unroll
            for (int g = 0; g < 4; g++) {
                MMA16816(oacc[2 * g],     ph[kc], vlf[g][0], vlf[g][1]);
                MMA16816(oacc[2 * g + 1], ph[kc], vlf[g][2], vlf[g][3]);
            }
#pragma unroll
            for (int g = 0; g < 4; g++) {
                MMA16816(oacc[2 * g],     pl[kc], vhf[g][0], vhf[g][1]);
                MMA16816(oacc[2 * g + 1], pl[kc], vhf[g][2], vhf[g][3]);
            }
        }
        __syncthreads();
    }

    // ---- epilogue: normalize, split hi/lo, write [B,S,DM] ----
    const int b = bh >> 4, h = bh & 15;
    const float inv0 = 1.0f / li0, inv1 = 1.0f / li1;
    const int r0 = q0 + wq + (l >> 2);
    const int r1 = r0 + 8;
#pragma unroll
    for (int nt = 0; nt < 8; nt++) {
        const int d = nt * 8 + (l & 3) * 2;
        const float x00 = oacc[nt][0] * inv0, x01 = oacc[nt][1] * inv0;
        const float x10 = oacc[nt][2] * inv1, x11 = oacc[nt][3] * inv1;
        __nv_bfloat16 h00, l00, h01, l01, h10, l10, h11, l11;
        split2(x00, h00, l00); split2(x01, h01, l01);
        split2(x10, h10, l10); split2(x11, h11, l11);
        const size_t i0 = ((size_t)(b * SEQ + r0)) * DM + h * HD + d;
        const size_t i1 = ((size_t)(b * SEQ + r1)) * DM + h * HD + d;
        *(__nv_bfloat162*)&oh_g[i0] = __nv_bfloat162(h00, h01);
        *(__nv_bfloat162*)&ol_g[i0] = __nv_bfloat162(l00, l01);
        *(__nv_bfloat162*)&oh_g[i1] = __nv_bfloat162(h10, h11);
        *(__nv_bfloat162*)&ol_g[i1] = __nv_bfloat162(l10, l11);
    }
}

// ---------------------------------------------------------------------------
extern "C" void kernel_launch(void* const* d_in, const int* in_sizes, int n_in,
                              void* d_out, int out_size) {
    (void)in_sizes; (void)n_in; (void)out_size;
    const float* Q  = (const float*)d_in[0];
    const float* K  = (const float*)d_in[1];
    const float* V  = (const float*)d_in[2];
    const float* Wq = (const float*)d_in[3];
    const float* bq = (const float*)d_in[4];
    const float* Wk = (const float*)d_in[5];
    const float* bk = (const float*)d_in[6];
    const float* Wv = (const float*)d_in[7];
    const float* bv = (const float*)d_in[8];
    const float* Wo = (const float*)d_in[9];
    const float* bo = (const float*)d_in[10];

    __nv_bfloat16 *qh, *ql, *kh, *kl, *vh, *vl, *ah, *al, *wh, *wl;
    cudaGetSymbolAddress((void**)&qh, g_qh);
    cudaGetSymbolAddress((void**)&ql, g_ql);
    cudaGetSymbolAddress((void**)&kh, g_kh);
    cudaGetSymbolAddress((void**)&kl, g_kl);
    cudaGetSymbolAddress((void**)&vh, g_vh);
    cudaGetSymbolAddress((void**)&vl, g_vl);
    cudaGetSymbolAddress((void**)&ah, g_ah);
    cudaGetSymbolAddress((void**)&al, g_al);
    cudaGetSymbolAddress((void**)&wh, g_wh);
    cudaGetSymbolAddress((void**)&wl, g_wl);

    cudaFuncSetAttribute(gemm_hmma<0>, cudaFuncAttributeMaxDynamicSharedMemorySize, GM_SMEM);
    cudaFuncSetAttribute(gemm_hmma<1>, cudaFuncAttributeMaxDynamicSharedMemorySize, GM_SMEM);
    cudaFuncSetAttribute(gemm_hmma<2>, cudaFuncAttributeMaxDynamicSharedMemorySize, GM_SMEM);
    cudaFuncSetAttribute(flash_hmma, cudaFuncAttributeMaxDynamicSharedMemorySize, FA_SMEM);

    const int ablk = (MTOT * DM / 4) / 1024;   // 2048
    const int wblk = (DM * DM / 4) / 1024;     // 256
    dim3 ggrid(MTOT / 128, DM / 128);          // (64, 8)

    // Q projection -> qh/ql [B,H,S,Dh]
    split_bf16<<<wblk, 256>>>(Wq, wh, wl);
    split_bf16<<<ablk, 256>>>(Q, ah, al);
    gemm_hmma<0><<<ggrid, 512, GM_SMEM>>>(ah, al, wh, wl, bq, qh, ql, nullptr);
    // K projection -> kh/kl [B,H,S,Dh]
    split_bf16<<<wblk, 256>>>(Wk, wh, wl);
    split_bf16<<<ablk, 256>>>(K, ah, al);
    gemm_hmma<0><<<ggrid, 512, GM_SMEM>>>(ah, al, wh, wl, bk, kh, kl, nullptr);
    // V projection -> vh/vl [B,H,Dh,S] (V^T)
    split_bf16<<<wblk, 256>>>(Wv, wh, wl);
    split_bf16<<<ablk, 256>>>(V, ah, al);
    gemm_hmma<2><<<ggrid, 512, GM_SMEM>>>(ah, al, wh, wl, bv, vh, vl, nullptr);

    // attention -> ah/al [B,S,DM] (hi/lo, ready for final projection)
    flash_hmma<<<dim3(SEQ / 128, BSZ * NH), 256, FA_SMEM>>>(qh, ql, kh, kl, vh, vl, ah, al);

    // output projection -> d_out fp32
    split_bf16<<<wblk, 256>>>(Wo, wh, wl);
    gemm_hmma<1><<<ggrid, 512, GM_SMEM>>>(ah, al, wh, wl, bo, nullptr, nullptr, (float*)d_out);
}

// round 13
// speedup vs baseline: 3.2242x; 1.0540x over previous
#include <cuda_runtime.h>
#include <cuda_bf16.h>
#include <cstdint>

#define DM   1024
#define NH   16
#define HD   64
#define BSZ  4
#define SEQ  2048
#define MTOT (BSZ * SEQ)   // 8192

// ---------------------------------------------------------------------------
// Scratch (no cudaMalloc allowed) — all bf16 hi/lo pairs
// ---------------------------------------------------------------------------
__device__ __nv_bfloat16 g_qh[BSZ * NH * SEQ * HD];   // [B,H,S,Dh]
__device__ __nv_bfloat16 g_ql[BSZ * NH * SEQ * HD];
__device__ __nv_bfloat16 g_kh[BSZ * NH * SEQ * HD];   // [B,H,S,Dh]
__device__ __nv_bfloat16 g_kl[BSZ * NH * SEQ * HD];
__device__ __nv_bfloat16 g_vh[BSZ * NH * SEQ * HD];   // [B,H,Dh,S] (V^T)
__device__ __nv_bfloat16 g_vl[BSZ * NH * SEQ * HD];
__device__ __nv_bfloat16 g_ah[MTOT * DM];             // attention out hi
__device__ __nv_bfloat16 g_al[MTOT * DM];             // attention out lo
// per-projection activation splits (Q,K,V inputs)
__device__ __nv_bfloat16 g_aqh[MTOT * DM], g_aql[MTOT * DM];
__device__ __nv_bfloat16 g_akh[MTOT * DM], g_akl[MTOT * DM];
__device__ __nv_bfloat16 g_avh[MTOT * DM], g_avl[MTOT * DM];
// per-projection weight splits
__device__ __nv_bfloat16 g_wqh[DM * DM], g_wql[DM * DM];
__device__ __nv_bfloat16 g_wkh[DM * DM], g_wkl[DM * DM];
__device__ __nv_bfloat16 g_wvh[DM * DM], g_wvl[DM * DM];
__device__ __nv_bfloat16 g_woh[DM * DM], g_wol[DM * DM];

// ---------------------------------------------------------------------------
// Family-portable PTX helpers (NO tcgen05 — harness ptxas targets sm_103)
// ---------------------------------------------------------------------------
__device__ __forceinline__ uint32_t smem_u32(const void* p) {
    uint32_t a;
    asm("{ .reg .u64 t; cvta.to.shared.u64 t, %1; cvt.u32.u64 %0, t; }"
        : "=r"(a) : "l"(p));
    return a;
}
#define SW128(o) ((o) ^ (((o) >> 3) & 0x70))

#define CP_ASYNC16(dst, src) \
    asm volatile("cp.async.cg.shared.global [%0], [%1], 16;" \
                 :: "r"(dst), "l"(src) : "memory")
#define CP_COMMIT() asm volatile("cp.async.commit_group;" ::: "memory")
#define CP_WAIT(n)  asm volatile("cp.async.wait_group %0;" :: "n"(n) : "memory")

#define LDMX4(r0, r1, r2, r3, addr) \
    asm volatile("ldmatrix.sync.aligned.m8n8.x4.shared.b16 {%0,%1,%2,%3}, [%4];" \
                 : "=r"(r0), "=r"(r1), "=r"(r2), "=r"(r3) : "r"(addr))

#define MMA16816(d, a, b0, b1) \
    asm volatile("mma.sync.aligned.m16n8k16.row.col.f32.bf16.bf16.f32 " \
                 "{%0,%1,%2,%3},{%4,%5,%6,%7},{%8,%9},{%0,%1,%2,%3};" \
                 : "+f"((d)[0]), "+f"((d)[1]), "+f"((d)[2]), "+f"((d)[3]) \
                 : "r"((a)[0]), "r"((a)[1]), "r"((a)[2]), "r"((a)[3]), \
                   "r"(b0), "r"(b1))

__device__ __forceinline__ uint32_t packbf(float lo, float hi) {
    __nv_bfloat162 t = __floats2bfloat162_rn(lo, hi);
    return *(uint32_t*)&t;
}
__device__ __forceinline__ void split2(float x, __nv_bfloat16& h, __nv_bfloat16& l) {
    h = __float2bfloat16(x);
    l = __float2bfloat16(x - __bfloat162float(h));
}

// ---------------------------------------------------------------------------
// Batched split fp32 -> bf16 hi/lo. blockIdx.y selects job. 4 float4s/thread.
// ---------------------------------------------------------------------------
__global__ __launch_bounds__(256) void split_multi(
    const float* __restrict__ in0, __nv_bfloat16* __restrict__ h0, __nv_bfloat16* __restrict__ l0,
    const float* __restrict__ in1, __nv_bfloat16* __restrict__ h1, __nv_bfloat16* __restrict__ l1,
    const float* __restrict__ in2, __nv_bfloat16* __restrict__ h2, __nv_bfloat16* __restrict__ l2,
    const float* __restrict__ in3, __nv_bfloat16* __restrict__ h3, __nv_bfloat16* __restrict__ l3) {
    const float* in;
    __nv_bfloat16 *hi, *lo;
    switch (blockIdx.y) {
        case 0:  in = in0; hi = h0; lo = l0; break;
        case 1:  in = in1; hi = h1; lo = l1; break;
        case 2:  in = in2; hi = h2; lo = l2; break;
        default: in = in3; hi = h3; lo = l3; break;
    }
    const int base = blockIdx.x * 1024 + threadIdx.x;
    float4 v[4];
#pragma unroll
    for (int u = 0; u < 4; u++) v[u] = ((const float4*)in)[base + u * 256];
#pragma unroll
    for (int u = 0; u < 4; u++) {
        const int i = base + u * 256;
        __nv_bfloat16 hx, hy, hz, hw, lx, ly, lz, lw;
        split2(v[u].x, hx, lx); split2(v[u].y, hy, ly);
        split2(v[u].z, hz, lz); split2(v[u].w, hw, lw);
        ((__nv_bfloat162*)hi)[2 * i]     = __nv_bfloat162(hx, hy);
        ((__nv_bfloat162*)hi)[2 * i + 1] = __nv_bfloat162(hz, hw);
        ((__nv_bfloat162*)lo)[2 * i]     = __nv_bfloat162(lx, ly);
        ((__nv_bfloat162*)lo)[2 * i + 1] = __nv_bfloat162(lz, lw);
    }
}

// ---------------------------------------------------------------------------
// Shared GEMM mainloop pieces (CTA 128x128, BK=64, 512 thr, double buffer)
// ---------------------------------------------------------------------------
#define GM_BUFSZ 65536
#define GM_SMEM  (2 * GM_BUFSZ)           // 131072

struct GemmJob {
    const __nv_bfloat16 *Ah, *Al, *Wh, *Wl;
    const float* bias;
    __nv_bfloat16 *Chi, *Clo;
};

// ---------------------------------------------------------------------------
// Batched QKV GEMM. grid (64, 8, 3); z selects job; z==2 -> transposed epi.
// ---------------------------------------------------------------------------
__global__ __launch_bounds__(512, 1) void gemm_qkv(GemmJob j0, GemmJob j1, GemmJob j2) {
    extern __shared__ __align__(1024) char smem[];
    const int z   = blockIdx.z;
    const GemmJob jb = (z == 0) ? j0 : ((z == 1) ? j1 : j2);
    const int tid = threadIdx.x;
    const int wid = tid >> 5;
    const int l   = tid & 31;
    const int m0  = blockIdx.x * 128;
    const int n0  = blockIdx.y * 128;
    const int wm  = (wid & 3) * 32;
    const int wn  = (wid >> 2) * 32;
    const uint32_t sb = smem_u32(smem);

    auto load_tiles = [&](int kb, uint32_t boff) {
#pragma unroll
        for (int t = 0; t < 2; t++) {
            const int f   = tid + t * 512;
            const int row = f >> 3, c = f & 7;
            const uint32_t o = SW128(row * 128 + c * 16);
            const size_t sa = (size_t)(m0 + row) * DM + kb * 64 + c * 8;
            const size_t sw = (size_t)(n0 + row) * DM + kb * 64 + c * 8;
            CP_ASYNC16(sb + boff + o,         jb.Ah + sa);
            CP_ASYNC16(sb + boff + 16384 + o, jb.Al + sa);
            CP_ASYNC16(sb + boff + 32768 + o, jb.Wh + sw);
            CP_ASYNC16(sb + boff + 49152 + o, jb.Wl + sw);
        }
    };

    float acc[2][4][4] = {};

    auto compute = [&](uint32_t bu) {
        const uint32_t bAh = bu, bAl = bu + 16384, bWh = bu + 32768, bWl = bu + 49152;
#pragma unroll
        for (int ks = 0; ks < 4; ks++) {
            uint32_t ah[2][4], al[2][4], bh[2][4], bl[2][4];
#pragma unroll
            for (int mt = 0; mt < 2; mt++) {
                const int r = wm + mt * 16 + (l & 15);
                const uint32_t off = SW128((uint32_t)(r * 128 + ks * 32 + (l >> 4) * 16));
                LDMX4(ah[mt][0], ah[mt][1], ah[mt][2], ah[mt][3], bAh + off);
                LDMX4(al[mt][0], al[mt][1], al[mt][2], al[mt][3], bAl + off);
            }
#pragma unroll
            for (int g = 0; g < 2; g++) {
                const int n = wn + g * 16 + (l & 7) + ((l >> 4) << 3);
                const uint32_t off = SW128((uint32_t)(n * 128 + ks * 32 + (((l >> 3) & 1) << 4)));
                LDMX4(bh[g][0], bh[g][1], bh[g][2], bh[g][3], bWh + off);
                LDMX4(bl[g][0], bl[g][1], bl[g][2], bl[g][3], bWl + off);
            }
#pragma unroll
            for (int mt = 0; mt < 2; mt++)
#pragma unroll
                for (int nt = 0; nt < 4; nt++) {
                    const int g = nt >> 1, p = (nt & 1) * 2;
                    MMA16816(acc[mt][nt], ah[mt], bh[g][p], bh[g][p + 1]);
                }
#pragma unroll
            for (int mt = 0; mt < 2; mt++)
#pragma unroll
                for (int nt = 0; nt < 4; nt++) {
                    const int g = nt >> 1, p = (nt & 1) * 2;
                    MMA16816(acc[mt][nt], ah[mt], bl[g][p], bl[g][p + 1]);
                }
#pragma unroll
            for (int mt = 0; mt < 2; mt++)
#pragma unroll
                for (int nt = 0; nt < 4; nt++) {
                    const int g = nt >> 1, p = (nt & 1) * 2;
                    MMA16816(acc[mt][nt], al[mt], bh[g][p], bh[g][p + 1]);
                }
        }
    };

    load_tiles(0, 0);
    CP_COMMIT();
    for (int i = 0; i < 16; i++) {
        if (i + 1 < 16) {
            load_tiles(i + 1, ((i + 1) & 1) * GM_BUFSZ);
            CP_COMMIT();
            CP_WAIT(1);
        } else {
            CP_WAIT(0);
        }
        __syncthreads();
        compute(sb + (i & 1) * GM_BUFSZ);
        __syncthreads();
    }

    if (z == 2) {
        // transposed epilogue -> [B,H,Dh,S] bf16 hi/lo  (V^T)
        float* Tr = (float*)(smem + wid * 4352);   // 32 x 33 floats
#pragma unroll
        for (int mt = 0; mt < 2; mt++)
#pragma unroll
            for (int nt = 0; nt < 4; nt++) {
                const int rl = mt * 16 + (l >> 2);
                const int cl = nt * 8 + (l & 3) * 2;
                Tr[cl * 33 + rl]           = acc[mt][nt][0];
                Tr[(cl + 1) * 33 + rl]     = acc[mt][nt][1];
                Tr[cl * 33 + rl + 8]       = acc[mt][nt][2];
                Tr[(cl + 1) * 33 + rl + 8] = acc[mt][nt][3];
            }
        __syncwarp();
        const int b  = m0 >> 11;
        const int s0 = (m0 & (SEQ - 1)) + wm;
#pragma unroll 4
        for (int c = 0; c < 32; c++) {
            const int n_g = n0 + wn + c;
            const int h = n_g >> 6, d = n_g & 63;
            const float x = Tr[c * 33 + l] + __ldg(&jb.bias[n_g]);
            __nv_bfloat16 hh, ll;
            split2(x, hh, ll);
            const size_t idx = ((size_t)((b * NH + h) * HD + d)) * SEQ + s0 + l;
            jb.Chi[idx] = hh;
            jb.Clo[idx] = ll;
        }
    } else {
        // scattered epilogue -> [B,H,S,Dh] bf16 hi/lo  (Q, K)
#pragma unroll
        for (int mt = 0; mt < 2; mt++)
#pragma unroll
            for (int nt = 0; nt < 4; nt++) {
                const int m_g = m0 + wm + mt * 16 + (l >> 2);
                const int n_g = n0 + wn + nt * 8 + (l & 3) * 2;
                const float b0 = __ldg(&jb.bias[n_g]);
                const float b1 = __ldg(&jb.bias[n_g + 1]);
                const float x00 = acc[mt][nt][0] + b0, x01 = acc[mt][nt][1] + b1;
                const float x10 = acc[mt][nt][2] + b0, x11 = acc[mt][nt][3] + b1;
                const int b = m_g >> 11, s = m_g & (SEQ - 1);
                const int h = n_g >> 6, d = n_g & 63;
                const size_t i0 = ((size_t)((b * NH + h) * SEQ + s)) * HD + d;
                const size_t i1 = ((size_t)((b * NH + h) * SEQ + s + 8)) * HD + d;
                __nv_bfloat16 h00, l00, h01, l01, h10, l10, h11, l11;
                split2(x00, h00, l00); split2(x01, h01, l01);
                split2(x10, h10, l10); split2(x11, h11, l11);
                *(__nv_bfloat162*)&jb.Chi[i0] = __nv_bfloat162(h00, h01);
                *(__nv_bfloat162*)&jb.Clo[i0] = __nv_bfloat162(l00, l01);
                *(__nv_bfloat162*)&jb.Chi[i1] = __nv_bfloat162(h10, h11);
                *(__nv_bfloat162*)&jb.Clo[i1] = __nv_bfloat162(l10, l11);
            }
    }
}

// ---------------------------------------------------------------------------
// Output projection GEMM (fp32 out, row-major)
// ---------------------------------------------------------------------------
__global__ __launch_bounds__(512, 1) void gemm_out(
    const __nv_bfloat16* __restrict__ Ah, const __nv_bfloat16* __restrict__ Al,
    const __nv_bfloat16* __restrict__ Wh, const __nv_bfloat16* __restrict__ Wl,
    const float* __restrict__ bias, float* __restrict__ Cf) {
    extern __shared__ __align__(1024) char smem[];
    const int tid = threadIdx.x;
    const int wid = tid >> 5;
    const int l   = tid & 31;
    const int m0  = blockIdx.x * 128;
    const int n0  = blockIdx.y * 128;
    const int wm  = (wid & 3) * 32;
    const int wn  = (wid >> 2) * 32;
    const uint32_t sb = smem_u32(smem);

    auto load_tiles = [&](int kb, uint32_t boff) {
#pragma unroll
        for (int t = 0; t < 2; t++) {
            const int f   = tid + t * 512;
            const int row = f >> 3, c = f & 7;
            const uint32_t o = SW128(row * 128 + c * 16);
            const size_t sa = (size_t)(m0 + row) * DM + kb * 64 + c * 8;
            const size_t sw = (size_t)(n0 + row) * DM + kb * 64 + c * 8;
            CP_ASYNC16(sb + boff + o,         Ah + sa);
            CP_ASYNC16(sb + boff + 16384 + o, Al + sa);
            CP_ASYNC16(sb + boff + 32768 + o, Wh + sw);
            CP_ASYNC16(sb + boff + 49152 + o, Wl + sw);
        }
    };

    float acc[2][4][4] = {};

    auto compute = [&](uint32_t bu) {
        const uint32_t bAh = bu, bAl = bu + 16384, bWh = bu + 32768, bWl = bu + 49152;
#pragma unroll
        for (int ks = 0; ks < 4; ks++) {
            uint32_t ah[2][4], al[2][4], bh[2][4], bl[2][4];
#pragma unroll
            for (int mt = 0; mt < 2; mt++) {
                const int r = wm + mt * 16 + (l & 15);
                const uint32_t off = SW128((uint32_t)(r * 128 + ks * 32 + (l >> 4) * 16));
                LDMX4(ah[mt][0], ah[mt][1], ah[mt][2], ah[mt][3], bAh + off);
                LDMX4(al[mt][0], al[mt][1], al[mt][2], al[mt][3], bAl + off);
            }
#pragma unroll
            for (int g = 0; g < 2; g++) {
                const int n = wn + g * 16 + (l & 7) + ((l >> 4) << 3);
                const uint32_t off = SW128((uint32_t)(n * 128 + ks * 32 + (((l >> 3) & 1) << 4)));
                LDMX4(bh[g][0], bh[g][1], bh[g][2], bh[g][3], bWh + off);
                LDMX4(bl[g][0], bl[g][1], bl[g][2], bl[g][3], bWl + off);
            }
#pragma unroll
            for (int mt = 0; mt < 2; mt++)
#pragma unroll
                for (int nt = 0; nt < 4; nt++) {
                    const int g = nt >> 1, p = (nt & 1) * 2;
                    MMA16816(acc[mt][nt], ah[mt], bh[g][p], bh[g][p + 1]);
                }
#pragma unroll
            for (int mt = 0; mt < 2; mt++)
#pragma unroll
                for (int nt = 0; nt < 4; nt++) {
                    const int g = nt >> 1, p = (nt & 1) * 2;
                    MMA16816(acc[mt][nt], ah[mt], bl[g][p], bl[g][p + 1]);
                }
#pragma unroll
            for (int mt = 0; mt < 2; mt++)
#pragma unroll
                for (int nt = 0; nt < 4; nt++) {
                    const int g = nt >> 1, p = (nt & 1) * 2;
                    MMA16816(acc[mt][nt], al[mt], bh[g][p], bh[g][p + 1]);
                }
        }
    };

    load_tiles(0, 0);
    CP_COMMIT();
    for (int i = 0; i < 16; i++) {
        if (i + 1 < 16) {
            load_tiles(i + 1, ((i + 1) & 1) * GM_BUFSZ);
            CP_COMMIT();
            CP_WAIT(1);
        } else {
            CP_WAIT(0);
        }
        __syncthreads();
        compute(sb + (i & 1) * GM_BUFSZ);
        __syncthreads();
    }

#pragma unroll
    for (int mt = 0; mt < 2; mt++)
#pragma unroll
        for (int nt = 0; nt < 4; nt++) {
            const int m_g = m0 + wm + mt * 16 + (l >> 2);
            const int n_g = n0 + wn + nt * 8 + (l & 3) * 2;
            const float b0 = __ldg(&bias[n_g]);
            const float b1 = __ldg(&bias[n_g + 1]);
            float2 v0, v1;
            v0.x = acc[mt][nt][0] + b0; v0.y = acc[mt][nt][1] + b1;
            v1.x = acc[mt][nt][2] + b0; v1.y = acc[mt][nt][3] + b1;
            *(float2*)&Cf[(size_t)m_g * DM + n_g]       = v0;
            *(float2*)&Cf[(size_t)(m_g + 8) * DM + n_g] = v1;
        }
}

// ---------------------------------------------------------------------------
// HMMA flash attention (exp2-domain softmax). CTA: 128 q x one (b,h).
// ---------------------------------------------------------------------------
#define FA_SMEM (32768 + 2 * 32768)
#define SCALE_LOG2 0.1803368801111204f   // 0.125 * log2(e)

__global__ __launch_bounds__(256) void flash_hmma(
    const __nv_bfloat16* __restrict__ qh_g, const __nv_bfloat16* __restrict__ ql_g,
    const __nv_bfloat16* __restrict__ kh_g, const __nv_bfloat16* __restrict__ kl_g,
    const __nv_bfloat16* __restrict__ vh_g, const __nv_bfloat16* __restrict__ vl_g,
    __nv_bfloat16* __restrict__ oh_g, __nv_bfloat16* __restrict__ ol_g) {
    extern __shared__ __align__(1024) char smem[];
    const int tid = threadIdx.x;
    const int wid = tid >> 5;
    const int l   = tid & 31;
    const int q0  = blockIdx.x * 128;
    const int bh  = blockIdx.y;
    const int wq  = wid * 16;
    const uint32_t sb  = smem_u32(smem);
    const uint32_t sQh = sb, sQl = sb + 16384;

    {
        const __nv_bfloat16* qh_s = qh_g + ((size_t)bh * SEQ + q0) * HD;
        const __nv_bfloat16* ql_s = ql_g + ((size_t)bh * SEQ + q0) * HD;
#pragma unroll
        for (int t = 0; t < 4; t++) {
            const int f = tid + t * 256;
            const int row = f >> 3, c = f & 7;
            const uint32_t o = SW128(row * 128 + c * 16);
            CP_ASYNC16(sQh + o, qh_s + row * HD + c * 8);
            CP_ASYNC16(sQl + o, ql_s + row * HD + c * 8);
        }
    }

    const __nv_bfloat16* kh_s = kh_g + (size_t)bh * SEQ * HD;
    const __nv_bfloat16* kl_s = kl_g + (size_t)bh * SEQ * HD;
    const __nv_bfloat16* vh_s = vh_g + (size_t)bh * HD * SEQ;
    const __nv_bfloat16* vl_s = vl_g + (size_t)bh * HD * SEQ;

    auto load_kv = [&](int j, uint32_t boff) {
        const int j0 = j * 64;
#pragma unroll
        for (int t = 0; t < 2; t++) {
            const int f = tid + t * 256;
            const int row = f >> 3, c = f & 7;
            const uint32_t o = SW128(row * 128 + c * 16);
            CP_ASYNC16(sb + boff + o,         kh_s + (size_t)(j0 + row) * HD + c * 8);
            CP_ASYNC16(sb + boff + 8192 + o,  kl_s + (size_t)(j0 + row) * HD + c * 8);
            CP_ASYNC16(sb + boff + 16384 + o, vh_s + (size_t)row * SEQ + j0 + c * 8);
            CP_ASYNC16(sb + boff + 24576 + o, vl_s + (size_t)row * SEQ + j0 + c * 8);
        }
    };

    float oacc[8][4] = {};
    float mi0 = -1e30f, mi1 = -1e30f, li0 = 0.0f, li1 = 0.0f;

    load_kv(0, 32768);
    CP_COMMIT();

    for (int j = 0; j < SEQ / 64; j++) {
        if (j + 1 < SEQ / 64) {
            load_kv(j + 1, 32768u + ((j + 1) & 1) * 32768u);
            CP_COMMIT();
            CP_WAIT(1);
        } else {
            CP_WAIT(0);
        }
        __syncthreads();

        const uint32_t bu  = sb + 32768u + (j & 1) * 32768u;
        const uint32_t bKh = bu, bKl = bu + 8192, bVh = bu + 16384, bVl = bu + 24576;

        // ---- scores S = Q K^T (x3 split) ----
        float sacc[8][4] = {};
#pragma unroll
        for (int ks = 0; ks < 4; ks++) {
            uint32_t qhf[4], qlf[4], khf[4][4], klf[4][4];
            {
                const int r = wq + (l & 15);
                const uint32_t off = SW128((uint32_t)(r * 128 + ks * 32 + (l >> 4) * 16));
                LDMX4(qhf[0], qhf[1], qhf[2], qhf[3], sQh + off);
                LDMX4(qlf[0], qlf[1], qlf[2], qlf[3], sQl + off);
            }
#pragma unroll
            for (int g = 0; g < 4; g++) {
                const int n = g * 16 + (l & 7) + ((l >> 4) << 3);
                const uint32_t off = SW128((uint32_t)(n * 128 + ks * 32 + (((l >> 3) & 1) << 4)));
                LDMX4(khf[g][0], khf[g][1], khf[g][2], khf[g][3], bKh + off);
                LDMX4(klf[g][0], klf[g][1], klf[g][2], klf[g][3], bKl + off);
            }
#pragma unroll
            for (int g = 0; g < 4; g++) {
                MMA16816(sacc[2 * g],     qhf, khf[g][0], khf[g][1]);
                MMA16816(sacc[2 * g + 1], qhf, khf[g][2], khf[g][3]);
            }
#pragma unroll
            for (int g = 0; g < 4; g++) {
                MMA16816(sacc[2 * g],     qhf, klf[g][0], klf[g][1]);
                MMA16816(sacc[2 * g + 1], qhf, klf[g][2], klf[g][3]);
            }
#pragma unroll
            for (int g = 0; g < 4; g++) {
                MMA16816(sacc[2 * g],     qlf, khf[g][0], khf[g][1]);
                MMA16816(sacc[2 * g + 1], qlf, khf[g][2], khf[g][3]);
            }
        }

        // ---- online softmax in exp2 domain ----
        float rm0 = -1e30f, rm1 = -1e30f;
#pragma unroll
        for (int t = 0; t < 8; t++) {
#pragma unroll
            for (int e = 0; e < 4; e++) sacc[t][e] *= SCALE_LOG2;
            rm0 = fmaxf(rm0, fmaxf(sacc[t][0], sacc[t][1]));
            rm1 = fmaxf(rm1, fmaxf(sacc[t][2], sacc[t][3]));
        }
        rm0 = fmaxf(rm0, __shfl_xor_sync(0xffffffffu, rm0, 1));
        rm0 = fmaxf(rm0, __shfl_xor_sync(0xffffffffu, rm0, 2));
        rm1 = fmaxf(rm1, __shfl_xor_sync(0xffffffffu, rm1, 1));
        rm1 = fmaxf(rm1, __shfl_xor_sync(0xffffffffu, rm1, 2));
        const float mn0 = fmaxf(mi0, rm0), mn1 = fmaxf(mi1, rm1);
        const float cr0 = exp2f(mi0 - mn0), cr1 = exp2f(mi1 - mn1);
        float rs0 = 0.0f, rs1 = 0.0f;
#pragma unroll
        for (int t = 0; t < 8; t++) {
            sacc[t][0] = exp2f(sacc[t][0] - mn0);
            sacc[t][1] = exp2f(sacc[t][1] - mn0);
            sacc[t][2] = exp2f(sacc[t][2] - mn1);
            sacc[t][3] = exp2f(sacc[t][3] - mn1);
            rs0 += sacc[t][0] + sacc[t][1];
            rs1 += sacc[t][2] + sacc[t][3];
        }
        rs0 += __shfl_xor_sync(0xffffffffu, rs0, 1);
        rs0 += __shfl_xor_sync(0xffffffffu, rs0, 2);
        rs1 += __shfl_xor_sync(0xffffffffu, rs1, 1);
        rs1 += __shfl_xor_sync(0xffffffffu, rs1, 2);
        li0 = li0 * cr0 + rs0;  mi0 = mn0;
        li1 = li1 * cr1 + rs1;  mi1 = mn1;
#pragma unroll
        for (int t = 0; t < 8; t++) {
            oacc[t][0] *= cr0; oacc[t][1] *= cr0;
            oacc[t][2] *= cr1; oacc[t][3] *= cr1;
        }

        // ---- pack P into A-fragments (hi/lo split), in-register ----
        uint32_t ph[4][4], pl[4][4];
#pragma unroll
        for (int kc = 0; kc < 4; kc++) {
#pragma unroll
            for (int half = 0; half < 2; half++) {
                const int t = 2 * kc + half;
                __nv_bfloat16 h0, l0, h1, l1, h2, l2, h3, l3;
                split2(sacc[t][0], h0, l0); split2(sacc[t][1], h1, l1);
                split2(sacc[t][2], h2, l2); split2(sacc[t][3], h3, l3);
                ph[kc][half * 2]     = packbf(__bfloat162float(h0), __bfloat162float(h1));
                ph[kc][half * 2 + 1] = packbf(__bfloat162float(h2), __bfloat162float(h3));
                pl[kc][half * 2]     = packbf(__bfloat162float(l0), __bfloat162float(l1));
                pl[kc][half * 2 + 1] = packbf(__bfloat162float(l2), __bfloat162float(l3));
            }
        }

        // ---- O += P V (x3 split) ----
#pragma unroll
        for (int kc = 0; kc < 4; kc++) {
            uint32_t vhf[4][4], vlf[4][4];
#pragma unroll
            for (int g = 0; g < 4; g++) {
                const int n = g * 16 + (l & 7) + ((l >> 4) << 3);
                const uint32_t off = SW128((uint32_t)(n * 128 + kc * 32 + (((l >> 3) & 1) << 4)));
                LDMX4(vhf[g][0], vhf[g][1], vhf[g][2], vhf[g][3], bVh + off);
                LDMX4(vlf[g][0], vlf[g][1], vlf[g][2], vlf[g][3], bVl + off);
            }
#pragma unroll
            for (int g = 0; g < 4; g++) {
                MMA16816(oacc[2 * g],     ph[kc], vhf[g][0], vhf[g][1]);
                MMA16816(oacc[2 * g + 1], ph[kc], vhf[g][2], vhf[g][3]);
            }
#pragma unroll
            for (int g = 0; g < 4; g++) {
                MMA16816(oacc[2 * g],     ph[kc], vlf[g][0], vlf[g][1]);
                MMA16816(oacc[2 * g + 1], ph[kc], vlf[g][2], vlf[g][3]);
            }
#pragma unroll
            for (int g = 0; g < 4; g++) {
                MMA16816(oacc[2 * g],     pl[kc], vhf[g][0], vhf[g][1]);
                MMA16816(oacc[2 * g + 1], pl[kc], vhf[g][2], vhf[g][3]);
            }
        }
        __syncthreads();
    }

    // ---- epilogue: normalize, split hi/lo, write [B,S,DM] ----
    const int b = bh >> 4, h = bh & 15;
    const float inv0 = 1.0f / li0, inv1 = 1.0f / li1;
    const int r0 = q0 + wq + (l >> 2);
    const int r1 = r0 + 8;
#pragma unroll
    for (int nt = 0; nt < 8; nt++) {
        const int d = nt * 8 + (l & 3) * 2;
        const float x00 = oacc[nt][0] * inv0, x01 = oacc[nt][1] * inv0;
        const float x10 = oacc[nt][2] * inv1, x11 = oacc[nt][3] * inv1;
        __nv_bfloat16 h00, l00, h01, l01, h10, l10, h11, l11;
        split2(x00, h00, l00); split2(x01, h01, l01);
        split2(x10, h10, l10); split2(x11, h11, l11);
        const size_t i0 = ((size_t)(b * SEQ + r0)) * DM + h * HD + d;
        const size_t i1 = ((size_t)(b * SEQ + r1)) * DM + h * HD + d;
        *(__nv_bfloat162*)&oh_g[i0] = __nv_bfloat162(h00, h01);
        *(__nv_bfloat162*)&ol_g[i0] = __nv_bfloat162(l00, l01);
        *(__nv_bfloat162*)&oh_g[i1] = __nv_bfloat162(h10, h11);
        *(__nv_bfloat162*)&ol_g[i1] = __nv_bfloat162(l10, l11);
    }
}

// ---------------------------------------------------------------------------
extern "C" void kernel_launch(void* const* d_in, const int* in_sizes, int n_in,
                              void* d_out, int out_size) {
    (void)in_sizes; (void)n_in; (void)out_size;
    const float* Q  = (const float*)d_in[0];
    const float* K  = (const float*)d_in[1];
    const float* V  = (const float*)d_in[2];
    const float* Wq = (const float*)d_in[3];
    const float* bq = (const float*)d_in[4];
    const float* Wk = (const float*)d_in[5];
    const float* bk = (const float*)d_in[6];
    const float* Wv = (const float*)d_in[7];
    const float* bv = (const float*)d_in[8];
    const float* Wo = (const float*)d_in[9];
    const float* bo = (const float*)d_in[10];

    __nv_bfloat16 *qh, *ql, *kh, *kl, *vh, *vl, *ah, *al;
    __nv_bfloat16 *aqh, *aql, *akh, *akl, *avh, *avl;
    __nv_bfloat16 *wqh, *wql, *wkh, *wkl, *wvh, *wvl, *woh, *wol;
    cudaGetSymbolAddress((void**)&qh, g_qh);   cudaGetSymbolAddress((void**)&ql, g_ql);
    cudaGetSymbolAddress((void**)&kh, g_kh);   cudaGetSymbolAddress((void**)&kl, g_kl);
    cudaGetSymbolAddress((void**)&vh, g_vh);   cudaGetSymbolAddress((void**)&vl, g_vl);
    cudaGetSymbolAddress((void**)&ah, g_ah);   cudaGetSymbolAddress((void**)&al, g_al);
    cudaGetSymbolAddress((void**)&aqh, g_aqh); cudaGetSymbolAddress((void**)&aql, g_aql);
    cudaGetSymbolAddress((void**)&akh, g_akh); cudaGetSymbolAddress((void**)&akl, g_akl);
    cudaGetSymbolAddress((void**)&avh, g_avh); cudaGetSymbolAddress((void**)&avl, g_avl);
    cudaGetSymbolAddress((void**)&wqh, g_wqh); cudaGetSymbolAddress((void**)&wql, g_wql);
    cudaGetSymbolAddress((void**)&wkh, g_wkh); cudaGetSymbolAddress((void**)&wkl, g_wkl);
    cudaGetSymbolAddress((void**)&wvh, g_wvh); cudaGetSymbolAddress((void**)&wvl, g_wvl);
    cudaGetSymbolAddress((void**)&woh, g_woh); cudaGetSymbolAddress((void**)&wol, g_wol);

    cudaFuncSetAttribute(gemm_qkv, cudaFuncAttributeMaxDynamicSharedMemorySize, GM_SMEM);
    cudaFuncSetAttribute(gemm_out, cudaFuncAttributeMaxDynamicSharedMemorySize, GM_SMEM);
    cudaFuncSetAttribute(flash_hmma, cudaFuncAttributeMaxDynamicSharedMemorySize, FA_SMEM);

    const int wblk = (DM * DM / 4) / 1024;     // 256
    const int ablk = (MTOT * DM / 4) / 1024;   // 2048

    // 1. split all 4 weights
    split_multi<<<dim3(wblk, 4), 256>>>(Wq, wqh, wql, Wk, wkh, wkl,
                                        Wv, wvh, wvl, Wo, woh, wol);
    // 2. split Q/K/V activations
    split_multi<<<dim3(ablk, 3), 256>>>(Q, aqh, aql, K, akh, akl,
                                        V, avh, avl, nullptr, nullptr, nullptr);
    // 3. batched QKV projections
    GemmJob jq = {aqh, aql, wqh, wql, bq, qh, ql};
    GemmJob jk = {akh, akl, wkh, wkl, bk, kh, kl};
    GemmJob jv = {avh, avl, wvh, wvl, bv, vh, vl};
    gemm_qkv<<<dim3(MTOT / 128, DM / 128, 3), 512, GM_SMEM>>>(jq, jk, jv);

    // 4. attention -> ah/al [B,S,DM]
    flash_hmma<<<dim3(SEQ / 128, BSZ * NH), 256, FA_SMEM>>>(qh, ql, kh, kl, vh, vl, ah, al);

    // 5. output projection -> d_out fp32
    gemm_out<<<dim3(MTOT / 128, DM / 128), 512, GM_SMEM>>>(ah, al, woh, wol, bo, (float*)d_out);
}

// round 14
// speedup vs baseline: 3.3720x; 1.0459x over previous
#include <cuda_runtime.h>
#include <cuda_bf16.h>
#include <cstdint>

#define DM   1024
#define NH   16
#define HD   64
#define BSZ  4
#define SEQ  2048
#define MTOT (BSZ * SEQ)   // 8192

// ---------------------------------------------------------------------------
// Scratch (no cudaMalloc allowed) — all bf16 hi/lo pairs
// ---------------------------------------------------------------------------
__device__ __nv_bfloat16 g_qh[BSZ * NH * SEQ * HD];   // [B,H,S,Dh] (pre-scaled)
__device__ __nv_bfloat16 g_ql[BSZ * NH * SEQ * HD];
__device__ __nv_bfloat16 g_kh[BSZ * NH * SEQ * HD];   // [B,H,S,Dh]
__device__ __nv_bfloat16 g_kl[BSZ * NH * SEQ * HD];
__device__ __nv_bfloat16 g_vh[BSZ * NH * SEQ * HD];   // [B,H,Dh,S] (V^T)
__device__ __nv_bfloat16 g_vl[BSZ * NH * SEQ * HD];
__device__ __nv_bfloat16 g_ah[MTOT * DM];             // attention out hi
__device__ __nv_bfloat16 g_al[MTOT * DM];             // attention out lo
__device__ __nv_bfloat16 g_aqh[MTOT * DM], g_aql[MTOT * DM];
__device__ __nv_bfloat16 g_akh[MTOT * DM], g_akl[MTOT * DM];
__device__ __nv_bfloat16 g_avh[MTOT * DM], g_avl[MTOT * DM];
__device__ __nv_bfloat16 g_wqh[DM * DM], g_wql[DM * DM];
__device__ __nv_bfloat16 g_wkh[DM * DM], g_wkl[DM * DM];
__device__ __nv_bfloat16 g_wvh[DM * DM], g_wvl[DM * DM];
__device__ __nv_bfloat16 g_woh[DM * DM], g_wol[DM * DM];

// ---------------------------------------------------------------------------
// Family-portable PTX helpers (NO tcgen05 — harness ptxas targets sm_103)
// ---------------------------------------------------------------------------
__device__ __forceinline__ uint32_t smem_u32(const void* p) {
    uint32_t a;
    asm("{ .reg .u64 t; cvta.to.shared.u64 t, %1; cvt.u32.u64 %0, t; }"
        : "=r"(a) : "l"(p));
    return a;
}
#define SW128(o) ((o) ^ (((o) >> 3) & 0x70))

#define CP_ASYNC16(dst, src) \
    asm volatile("cp.async.cg.shared.global [%0], [%1], 16;" \
                 :: "r"(dst), "l"(src) : "memory")
#define CP_COMMIT() asm volatile("cp.async.commit_group;" ::: "memory")
#define CP_WAIT(n)  asm volatile("cp.async.wait_group %0;" :: "n"(n) : "memory")

#define LDMX4(r0, r1, r2, r3, addr) \
    asm volatile("ldmatrix.sync.aligned.m8n8.x4.shared.b16 {%0,%1,%2,%3}, [%4];" \
                 : "=r"(r0), "=r"(r1), "=r"(r2), "=r"(r3) : "r"(addr))

#define MMA16816(d, a, b0, b1) \
    asm volatile("mma.sync.aligned.m16n8k16.row.col.f32.bf16.bf16.f32 " \
                 "{%0,%1,%2,%3},{%4,%5,%6,%7},{%8,%9},{%0,%1,%2,%3};" \
                 : "+f"((d)[0]), "+f"((d)[1]), "+f"((d)[2]), "+f"((d)[3]) \
                 : "r"((a)[0]), "r"((a)[1]), "r"((a)[2]), "r"((a)[3]), \
                   "r"(b0), "r"(b1))

__device__ __forceinline__ uint32_t packbf(float lo, float hi) {
    __nv_bfloat162 t = __floats2bfloat162_rn(lo, hi);
    return *(uint32_t*)&t;
}
__device__ __forceinline__ void split2(float x, __nv_bfloat16& h, __nv_bfloat16& l) {
    h = __float2bfloat16(x);
    l = __float2bfloat16(x - __bfloat162float(h));
}

#define SCALE_LOG2 0.1803368801111204f   // 0.125 * log2(e)

// ---------------------------------------------------------------------------
// Batched split fp32 -> bf16 hi/lo. blockIdx.y selects job. 4 float4s/thread.
// ---------------------------------------------------------------------------
__global__ __launch_bounds__(256) void split_multi(
    const float* __restrict__ in0, __nv_bfloat16* __restrict__ h0, __nv_bfloat16* __restrict__ l0,
    const float* __restrict__ in1, __nv_bfloat16* __restrict__ h1, __nv_bfloat16* __restrict__ l1,
    const float* __restrict__ in2, __nv_bfloat16* __restrict__ h2, __nv_bfloat16* __restrict__ l2,
    const float* __restrict__ in3, __nv_bfloat16* __restrict__ h3, __nv_bfloat16* __restrict__ l3) {
    const float* in;
    __nv_bfloat16 *hi, *lo;
    switch (blockIdx.y) {
        case 0:  in = in0; hi = h0; lo = l0; break;
        case 1:  in = in1; hi = h1; lo = l1; break;
        case 2:  in = in2; hi = h2; lo = l2; break;
        default: in = in3; hi = h3; lo = l3; break;
    }
    const int base = blockIdx.x * 1024 + threadIdx.x;
    float4 v[4];
#pragma unroll
    for (int u = 0; u < 4; u++) v[u] = ((const float4*)in)[base + u * 256];
#pragma unroll
    for (int u = 0; u < 4; u++) {
        const int i = base + u * 256;
        __nv_bfloat16 hx, hy, hz, hw, lx, ly, lz, lw;
        split2(v[u].x, hx, lx); split2(v[u].y, hy, ly);
        split2(v[u].z, hz, lz); split2(v[u].w, hw, lw);
        ((__nv_bfloat162*)hi)[2 * i]     = __nv_bfloat162(hx, hy);
        ((__nv_bfloat162*)hi)[2 * i + 1] = __nv_bfloat162(hz, hw);
        ((__nv_bfloat162*)lo)[2 * i]     = __nv_bfloat162(lx, ly);
        ((__nv_bfloat162*)lo)[2 * i + 1] = __nv_bfloat162(lz, lw);
    }
}

// ---------------------------------------------------------------------------
// Shared GEMM config (CTA 128x128, BK=64, 512 thr, double buffer)
// ---------------------------------------------------------------------------
#define GM_BUFSZ 65536
#define GM_SMEM  (2 * GM_BUFSZ)           // 131072

struct GemmJob {
    const __nv_bfloat16 *Ah, *Al, *Wh, *Wl;
    const float* bias;
    __nv_bfloat16 *Chi, *Clo;
    float scale;                           // applied to (acc + bias) pre-split
};

// ---------------------------------------------------------------------------
// Batched QKV GEMM. grid (64, 8, 3); z selects job; z==2 -> transposed epi.
// ---------------------------------------------------------------------------
__global__ __launch_bounds__(512, 1) void gemm_qkv(GemmJob j0, GemmJob j1, GemmJob j2) {
    extern __shared__ __align__(1024) char smem[];
    const int z   = blockIdx.z;
    const GemmJob jb = (z == 0) ? j0 : ((z == 1) ? j1 : j2);
    const int tid = threadIdx.x;
    const int wid = tid >> 5;
    const int l   = tid & 31;
    const int m0  = blockIdx.x * 128;
    const int n0  = blockIdx.y * 128;
    const int wm  = (wid & 3) * 32;
    const int wn  = (wid >> 2) * 32;
    const uint32_t sb = smem_u32(smem);

    auto load_tiles = [&](int kb, uint32_t boff) {
#pragma unroll
        for (int t = 0; t < 2; t++) {
            const int f   = tid + t * 512;
            const int row = f >> 3, c = f & 7;
            const uint32_t o = SW128(row * 128 + c * 16);
            const size_t sa = (size_t)(m0 + row) * DM + kb * 64 + c * 8;
            const size_t sw = (size_t)(n0 + row) * DM + kb * 64 + c * 8;
            CP_ASYNC16(sb + boff + o,         jb.Ah + sa);
            CP_ASYNC16(sb + boff + 16384 + o, jb.Al + sa);
            CP_ASYNC16(sb + boff + 32768 + o, jb.Wh + sw);
            CP_ASYNC16(sb + boff + 49152 + o, jb.Wl + sw);
        }
    };

    float acc[2][4][4] = {};

    auto compute = [&](uint32_t bu) {
        const uint32_t bAh = bu, bAl = bu + 16384, bWh = bu + 32768, bWl = bu + 49152;
#pragma unroll
        for (int ks = 0; ks < 4; ks++) {
            uint32_t ah[2][4], al[2][4], bh[2][4], bl[2][4];
#pragma unroll
            for (int mt = 0; mt < 2; mt++) {
                const int r = wm + mt * 16 + (l & 15);
                const uint32_t off = SW128((uint32_t)(r * 128 + ks * 32 + (l >> 4) * 16));
                LDMX4(ah[mt][0], ah[mt][1], ah[mt][2], ah[mt][3], bAh + off);
                LDMX4(al[mt][0], al[mt][1], al[mt][2], al[mt][3], bAl + off);
            }
#pragma unroll
            for (int g = 0; g < 2; g++) {
                const int n = wn + g * 16 + (l & 7) + ((l >> 4) << 3);
                const uint32_t off = SW128((uint32_t)(n * 128 + ks * 32 + (((l >> 3) & 1) << 4)));
                LDMX4(bh[g][0], bh[g][1], bh[g][2], bh[g][3], bWh + off);
                LDMX4(bl[g][0], bl[g][1], bl[g][2], bl[g][3], bWl + off);
            }
#pragma unroll
            for (int mt = 0; mt < 2; mt++)
#pragma unroll
                for (int nt = 0; nt < 4; nt++) {
                    const int g = nt >> 1, p = (nt & 1) * 2;
                    MMA16816(acc[mt][nt], ah[mt], bh[g][p], bh[g][p + 1]);
                }
#pragma unroll
            for (int mt = 0; mt < 2; mt++)
#pragma unroll
                for (int nt = 0; nt < 4; nt++) {
                    const int g = nt >> 1, p = (nt & 1) * 2;
                    MMA16816(acc[mt][nt], ah[mt], bl[g][p], bl[g][p + 1]);
                }
#pragma unroll
            for (int mt = 0; mt < 2; mt++)
#pragma unroll
                for (int nt = 0; nt < 4; nt++) {
                    const int g = nt >> 1, p = (nt & 1) * 2;
                    MMA16816(acc[mt][nt], al[mt], bh[g][p], bh[g][p + 1]);
                }
        }
    };

    load_tiles(0, 0);
    CP_COMMIT();
    for (int i = 0; i < 16; i++) {
        if (i + 1 < 16) {
            load_tiles(i + 1, ((i + 1) & 1) * GM_BUFSZ);
            CP_COMMIT();
            CP_WAIT(1);
        } else {
            CP_WAIT(0);
        }
        __syncthreads();
        compute(sb + (i & 1) * GM_BUFSZ);
        __syncthreads();
    }

    if (z == 2) {
        // transposed epilogue -> [B,H,Dh,S] bf16 hi/lo  (V^T)
        float* Tr = (float*)(smem + wid * 4352);   // 32 x 33 floats
#pragma unroll
        for (int mt = 0; mt < 2; mt++)
#pragma unroll
            for (int nt = 0; nt < 4; nt++) {
                const int rl = mt * 16 + (l >> 2);
                const int cl = nt * 8 + (l & 3) * 2;
                Tr[cl * 33 + rl]           = acc[mt][nt][0];
                Tr[(cl + 1) * 33 + rl]     = acc[mt][nt][1];
                Tr[cl * 33 + rl + 8]       = acc[mt][nt][2];
                Tr[(cl + 1) * 33 + rl + 8] = acc[mt][nt][3];
            }
        __syncwarp();
        const int b  = m0 >> 11;
        const int s0 = (m0 & (SEQ - 1)) + wm;
#pragma unroll 4
        for (int c = 0; c < 32; c++) {
            const int n_g = n0 + wn + c;
            const int h = n_g >> 6, d = n_g & 63;
            const float x = (Tr[c * 33 + l] + __ldg(&jb.bias[n_g])) * jb.scale;
            __nv_bfloat16 hh, ll;
            split2(x, hh, ll);
            const size_t idx = ((size_t)((b * NH + h) * HD + d)) * SEQ + s0 + l;
            jb.Chi[idx] = hh;
            jb.Clo[idx] = ll;
        }
    } else {
        // scattered epilogue -> [B,H,S,Dh] bf16 hi/lo  (Q, K)
#pragma unroll
        for (int mt = 0; mt < 2; mt++)
#pragma unroll
            for (int nt = 0; nt < 4; nt++) {
                const int m_g = m0 + wm + mt * 16 + (l >> 2);
                const int n_g = n0 + wn + nt * 8 + (l & 3) * 2;
                const float b0 = __ldg(&jb.bias[n_g]);
                const float b1 = __ldg(&jb.bias[n_g + 1]);
                const float x00 = (acc[mt][nt][0] + b0) * jb.scale;
                const float x01 = (acc[mt][nt][1] + b1) * jb.scale;
                const float x10 = (acc[mt][nt][2] + b0) * jb.scale;
                const float x11 = (acc[mt][nt][3] + b1) * jb.scale;
                const int b = m_g >> 11, s = m_g & (SEQ - 1);
                const int h = n_g >> 6, d = n_g & 63;
                const size_t i0 = ((size_t)((b * NH + h) * SEQ + s)) * HD + d;
                const size_t i1 = ((size_t)((b * NH + h) * SEQ + s + 8)) * HD + d;
                __nv_bfloat16 h00, l00, h01, l01, h10, l10, h11, l11;
                split2(x00, h00, l00); split2(x01, h01, l01);
                split2(x10, h10, l10); split2(x11, h11, l11);
                *(__nv_bfloat162*)&jb.Chi[i0] = __nv_bfloat162(h00, h01);
                *(__nv_bfloat162*)&jb.Clo[i0] = __nv_bfloat162(l00, l01);
                *(__nv_bfloat162*)&jb.Chi[i1] = __nv_bfloat162(h10, h11);
                *(__nv_bfloat162*)&jb.Clo[i1] = __nv_bfloat162(l10, l11);
            }
    }
}

// ---------------------------------------------------------------------------
// Output projection GEMM (fp32 out, row-major)
// ---------------------------------------------------------------------------
__global__ __launch_bounds__(512, 1) void gemm_out(
    const __nv_bfloat16* __restrict__ Ah, const __nv_bfloat16* __restrict__ Al,
    const __nv_bfloat16* __restrict__ Wh, const __nv_bfloat16* __restrict__ Wl,
    const float* __restrict__ bias, float* __restrict__ Cf) {
    extern __shared__ __align__(1024) char smem[];
    const int tid = threadIdx.x;
    const int wid = tid >> 5;
    const int l   = tid & 31;
    const int m0  = blockIdx.x * 128;
    const int n0  = blockIdx.y * 128;
    const int wm  = (wid & 3) * 32;
    const int wn  = (wid >> 2) * 32;
    const uint32_t sb = smem_u32(smem);

    auto load_tiles = [&](int kb, uint32_t boff) {
#pragma unroll
        for (int t = 0; t < 2; t++) {
            const int f   = tid + t * 512;
            const int row = f >> 3, c = f & 7;
            const uint32_t o = SW128(row * 128 + c * 16);
            const size_t sa = (size_t)(m0 + row) * DM + kb * 64 + c * 8;
            const size_t sw = (size_t)(n0 + row) * DM + kb * 64 + c * 8;
            CP_ASYNC16(sb + boff + o,         Ah + sa);
            CP_ASYNC16(sb + boff + 16384 + o, Al + sa);
            CP_ASYNC16(sb + boff + 32768 + o, Wh + sw);
            CP_ASYNC16(sb + boff + 49152 + o, Wl + sw);
        }
    };

    float acc[2][4][4] = {};

    auto compute = [&](uint32_t bu) {
        const uint32_t bAh = bu, bAl = bu + 16384, bWh = bu + 32768, bWl = bu + 49152;
#pragma unroll
        for (int ks = 0; ks < 4; ks++) {
            uint32_t ah[2][4], al[2][4], bh[2][4], bl[2][4];
#pragma unroll
            for (int mt = 0; mt < 2; mt++) {
                const int r = wm + mt * 16 + (l & 15);
                const uint32_t off = SW128((uint32_t)(r * 128 + ks * 32 + (l >> 4) * 16));
                LDMX4(ah[mt][0], ah[mt][1], ah[mt][2], ah[mt][3], bAh + off);
                LDMX4(al[mt][0], al[mt][1], al[mt][2], al[mt][3], bAl + off);
            }
#pragma unroll
            for (int g = 0; g < 2; g++) {
                const int n = wn + g * 16 + (l & 7) + ((l >> 4) << 3);
                const uint32_t off = SW128((uint32_t)(n * 128 + ks * 32 + (((l >> 3) & 1) << 4)));
                LDMX4(bh[g][0], bh[g][1], bh[g][2], bh[g][3], bWh + off);
                LDMX4(bl[g][0], bl[g][1], bl[g][2], bl[g][3], bWl + off);
            }
#pragma unroll
            for (int mt = 0; mt < 2; mt++)
#pragma unroll
                for (int nt = 0; nt < 4; nt++) {
                    const int g = nt >> 1, p = (nt & 1) * 2;
                    MMA16816(acc[mt][nt], ah[mt], bh[g][p], bh[g][p + 1]);
                }
#pragma unroll
            for (int mt = 0; mt < 2; mt++)
#pragma unroll
                for (int nt = 0; nt < 4; nt++) {
                    const int g = nt >> 1, p = (nt & 1) * 2;
                    MMA16816(acc[mt][nt], ah[mt], bl[g][p], bl[g][p + 1]);
                }
#pragma unroll
            for (int mt = 0; mt < 2; mt++)
#pragma unroll
                for (int nt = 0; nt < 4; nt++) {
                    const int g = nt >> 1, p = (nt & 1) * 2;
                    MMA16816(acc[mt][nt], al[mt], bh[g][p], bh[g][p + 1]);
                }
        }
    };

    load_tiles(0, 0);
    CP_COMMIT();
    for (int i = 0; i < 16; i++) {
        if (i + 1 < 16) {
            load_tiles(i + 1, ((i + 1) & 1) * GM_BUFSZ);
            CP_COMMIT();
            CP_WAIT(1);
        } else {
            CP_WAIT(0);
        }
        __syncthreads();
        compute(sb + (i & 1) * GM_BUFSZ);
        __syncthreads();
    }

#pragma unroll
    for (int mt = 0; mt < 2; mt++)
#pragma unroll
        for (int nt = 0; nt < 4; nt++) {
            const int m_g = m0 + wm + mt * 16 + (l >> 2);
            const int n_g = n0 + wn + nt * 8 + (l & 3) * 2;
            const float b0 = __ldg(&bias[n_g]);
            const float b1 = __ldg(&bias[n_g + 1]);
            float2 v0, v1;
            v0.x = acc[mt][nt][0] + b0; v0.y = acc[mt][nt][1] + b1;
            v1.x = acc[mt][nt][2] + b0; v1.y = acc[mt][nt][3] + b1;
            *(float2*)&Cf[(size_t)m_g * DM + n_g]       = v0;
            *(float2*)&Cf[(size_t)(m_g + 8) * DM + n_g] = v1;
        }
}

// ---------------------------------------------------------------------------
// HMMA flash attention (exp2-domain softmax, Q pre-scaled at projection).
// CTA: 128 q x one (b,h). __launch_bounds__(256,2) -> 2 CTAs/SM (regs<=128).
// ---------------------------------------------------------------------------
#define FA_SMEM (32768 + 2 * 32768)

__global__ __launch_bounds__(256, 2) void flash_hmma(
    const __nv_bfloat16* __restrict__ qh_g, const __nv_bfloat16* __restrict__ ql_g,
    const __nv_bfloat16* __restrict__ kh_g, const __nv_bfloat16* __restrict__ kl_g,
    const __nv_bfloat16* __restrict__ vh_g, const __nv_bfloat16* __restrict__ vl_g,
    __nv_bfloat16* __restrict__ oh_g, __nv_bfloat16* __restrict__ ol_g) {
    extern __shared__ __align__(1024) char smem[];
    const int tid = threadIdx.x;
    const int wid = tid >> 5;
    const int l   = tid & 31;
    const int q0  = blockIdx.x * 128;
    const int bh  = blockIdx.y;
    const int wq  = wid * 16;
    const uint32_t sb  = smem_u32(smem);
    const uint32_t sQh = sb, sQl = sb + 16384;

    {
        const __nv_bfloat16* qh_s = qh_g + ((size_t)bh * SEQ + q0) * HD;
        const __nv_bfloat16* ql_s = ql_g + ((size_t)bh * SEQ + q0) * HD;
#pragma unroll
        for (int t = 0; t < 4; t++) {
            const int f = tid + t * 256;
            const int row = f >> 3, c = f & 7;
            const uint32_t o = SW128(row * 128 + c * 16);
            CP_ASYNC16(sQh + o, qh_s + row * HD + c * 8);
            CP_ASYNC16(sQl + o, ql_s + row * HD + c * 8);
        }
    }

    const __nv_bfloat16* kh_s = kh_g + (size_t)bh * SEQ * HD;
    const __nv_bfloat16* kl_s = kl_g + (size_t)bh * SEQ * HD;
    const __nv_bfloat16* vh_s = vh_g + (size_t)bh * HD * SEQ;
    const __nv_bfloat16* vl_s = vl_g + (size_t)bh * HD * SEQ;

    auto load_kv = [&](int j, uint32_t boff) {
        const int j0 = j * 64;
#pragma unroll
        for (int t = 0; t < 2; t++) {
            const int f = tid + t * 256;
            const int row = f >> 3, c = f & 7;
            const uint32_t o = SW128(row * 128 + c * 16);
            CP_ASYNC16(sb + boff + o,         kh_s + (size_t)(j0 + row) * HD + c * 8);
            CP_ASYNC16(sb + boff + 8192 + o,  kl_s + (size_t)(j0 + row) * HD + c * 8);
            CP_ASYNC16(sb + boff + 16384 + o, vh_s + (size_t)row * SEQ + j0 + c * 8);
            CP_ASYNC16(sb + boff + 24576 + o, vl_s + (size_t)row * SEQ + j0 + c * 8);
        }
    };

    float oacc[8][4] = {};
    float mi0 = -1e30f, mi1 = -1e30f, li0 = 0.0f, li1 = 0.0f;

    load_kv(0, 32768);
    CP_COMMIT();

    for (int j = 0; j < SEQ / 64; j++) {
        if (j + 1 < SEQ / 64) {
            load_kv(j + 1, 32768u + ((j + 1) & 1) * 32768u);
            CP_COMMIT();
            CP_WAIT(1);
        } else {
            CP_WAIT(0);
        }
        __syncthreads();

        const uint32_t bu  = sb + 32768u + (j & 1) * 32768u;
        const uint32_t bKh = bu, bKl = bu + 8192, bVh = bu + 16384, bVl = bu + 24576;

        // ---- scores S = Q K^T (x3 split, already in log2 units) ----
        float sacc[8][4] = {};
#pragma unroll
        for (int ks = 0; ks < 4; ks++) {
            uint32_t qhf[4], qlf[4], khf[4][4], klf[4][4];
            {
                const int r = wq + (l & 15);
                const uint32_t off = SW128((uint32_t)(r * 128 + ks * 32 + (l >> 4) * 16));
                LDMX4(qhf[0], qhf[1], qhf[2], qhf[3], sQh + off);
                LDMX4(qlf[0], qlf[1], qlf[2], qlf[3], sQl + off);
            }
#pragma unroll
            for (int g = 0; g < 4; g++) {
                const int n = g * 16 + (l & 7) + ((l >> 4) << 3);
                const uint32_t off = SW128((uint32_t)(n * 128 + ks * 32 + (((l >> 3) & 1) << 4)));
                LDMX4(khf[g][0], khf[g][1], khf[g][2], khf[g][3], bKh + off);
                LDMX4(klf[g][0], klf[g][1], klf[g][2], klf[g][3], bKl + off);
            }
#pragma unroll
            for (int g = 0; g < 4; g++) {
                MMA16816(sacc[2 * g],     qhf, khf[g][0], khf[g][1]);
                MMA16816(sacc[2 * g + 1], qhf, khf[g][2], khf[g][3]);
            }
#pragma unroll
            for (int g = 0; g < 4; g++) {
                MMA16816(sacc[2 * g],     qhf, klf[g][0], klf[g][1]);
                MMA16816(sacc[2 * g + 1], qhf, klf[g][2], klf[g][3]);
            }
#pragma unroll
            for (int g = 0; g < 4; g++) {
                MMA16816(sacc[2 * g],     qlf, khf[g][0], khf[g][1]);
                MMA16816(sacc[2 * g + 1], qlf, khf[g][2], khf[g][3]);
            }
        }

        // ---- online softmax (exp2 domain, no pre-scale needed) ----
        float rm0 = -1e30f, rm1 = -1e30f;
#pragma unroll
        for (int t = 0; t < 8; t++) {
            rm0 = fmaxf(rm0, fmaxf(sacc[t][0], sacc[t][1]));
            rm1 = fmaxf(rm1, fmaxf(sacc[t][2], sacc[t][3]));
        }
        rm0 = fmaxf(rm0, __shfl_xor_sync(0xffffffffu, rm0, 1));
        rm0 = fmaxf(rm0, __shfl_xor_sync(0xffffffffu, rm0, 2));
        rm1 = fmaxf(rm1, __shfl_xor_sync(0xffffffffu, rm1, 1));
        rm1 = fmaxf(rm1, __shfl_xor_sync(0xffffffffu, rm1, 2));
        const float mn0 = fmaxf(mi0, rm0), mn1 = fmaxf(mi1, rm1);
        const float cr0 = exp2f(mi0 - mn0), cr1 = exp2f(mi1 - mn1);
        float rs0 = 0.0f, rs1 = 0.0f;
#pragma unroll
        for (int t = 0; t < 8; t++) {
            sacc[t][0] = exp2f(sacc[t][0] - mn0);
            sacc[t][1] = exp2f(sacc[t][1] - mn0);
            sacc[t][2] = exp2f(sacc[t][2] - mn1);
            sacc[t][3] = exp2f(sacc[t][3] - mn1);
            rs0 += sacc[t][0] + sacc[t][1];
            rs1 += sacc[t][2] + sacc[t][3];
        }
        rs0 += __shfl_xor_sync(0xffffffffu, rs0, 1);
        rs0 += __shfl_xor_sync(0xffffffffu, rs0, 2);
        rs1 += __shfl_xor_sync(0xffffffffu, rs1, 1);
        rs1 += __shfl_xor_sync(0xffffffffu, rs1, 2);
        li0 = li0 * cr0 + rs0;  mi0 = mn0;
        li1 = li1 * cr1 + rs1;  mi1 = mn1;
#pragma unroll
        for (int t = 0; t < 8; t++) {
            oacc[t][0] *= cr0; oacc[t][1] *= cr0;
            oacc[t][2] *= cr1; oacc[t][3] *= cr1;
        }

        // ---- pack P into A-fragments (hi/lo split), in-register ----
        uint32_t ph[4][4], pl[4][4];
#pragma unroll
        for (int kc = 0; kc < 4; kc++) {
#pragma unroll
            for (int half = 0; half < 2; half++) {
                const int t = 2 * kc + half;
                __nv_bfloat16 h0, l0, h1, l1, h2, l2, h3, l3;
                split2(sacc[t][0], h0, l0); split2(sacc[t][1], h1, l1);
                split2(sacc[t][2], h2, l2); split2(sacc[t][3], h3, l3);
                ph[kc][half * 2]     = packbf(__bfloat162float(h0), __bfloat162float(h1));
                ph[kc][half * 2 + 1] = packbf(__bfloat162float(h2), __bfloat162float(h3));
                pl[kc][half * 2]     = packbf(__bfloat162float(l0), __bfloat162float(l1));
                pl[kc][half * 2 + 1] = packbf(__bfloat162float(l2), __bfloat162float(l3));
            }
        }

        // ---- O += P V (x3 split) ----
#pragma unroll
        for (int kc = 0; kc < 4; kc++) {
            uint32_t vhf[4][4], vlf[4][4];
#pragma unroll
            for (int g = 0; g < 4; g++) {
                const int n = g * 16 + (l & 7) + ((l >> 4) << 3);
                const uint32_t off = SW128((uint32_t)(n * 128 + kc * 32 + (((l >> 3) & 1) << 4)));
                LDMX4(vhf[g][0], vhf[g][1], vhf[g][2], vhf[g][3], bVh + off);
                LDMX4(vlf[g][0], vlf[g][1], vlf[g][2], vlf[g][3], bVl + off);
            }
#pragma unroll
            for (int g = 0; g < 4; g++) {
                MMA16816(oacc[2 * g],     ph[kc], vhf[g][0], vhf[g][1]);
                MMA16816(oacc[2 * g + 1], ph[kc], vhf[g][2], vhf[g][3]);
            }
#pragma unroll
            for (int g = 0; g < 4; g++) {
                MMA16816(oacc[2 * g],     ph[kc], vlf[g][0], vlf[g][1]);
                MMA16816(oacc[2 * g + 1], ph[kc], vlf[g][2], vlf[g][3]);
            }
#pragma unroll
            for (int g = 0; g < 4; g++) {
                MMA16816(oacc[2 * g],     pl[kc], vhf[g][0], vhf[g][1]);
                MMA16816(oacc[2 * g + 1], pl[kc], vhf[g][2], vhf[g][3]);
            }
        }
        __syncthreads();
    }

    // ---- epilogue: normalize, split hi/lo, write [B,S,DM] ----
    const int b = bh >> 4, h = bh & 15;
    const float inv0 = 1.0f / li0, inv1 = 1.0f / li1;
    const int r0 = q0 + wq + (l >> 2);
    const int r1 = r0 + 8;
#pragma unroll
    for (int nt = 0; nt < 8; nt++) {
        const int d = nt * 8 + (l & 3) * 2;
        const float x00 = oacc[nt][0] * inv0, x01 = oacc[nt][1] * inv0;
        const float x10 = oacc[nt][2] * inv1, x11 = oacc[nt][3] * inv1;
        __nv_bfloat16 h00, l00, h01, l01, h10, l10, h11, l11;
        split2(x00, h00, l00); split2(x01, h01, l01);
        split2(x10, h10, l10); split2(x11, h11, l11);
        const size_t i0 = ((size_t)(b * SEQ + r0)) * DM + h * HD + d;
        const size_t i1 = ((size_t)(b * SEQ + r1)) * DM + h * HD + d;
        *(__nv_bfloat162*)&oh_g[i0] = __nv_bfloat162(h00, h01);
        *(__nv_bfloat162*)&ol_g[i0] = __nv_bfloat162(l00, l01);
        *(__nv_bfloat162*)&oh_g[i1] = __nv_bfloat162(h10, h11);
        *(__nv_bfloat162*)&ol_g[i1] = __nv_bfloat162(l10, l11);
    }
}

// ---------------------------------------------------------------------------
extern "C" void kernel_launch(void* const* d_in, const int* in_sizes, int n_in,
                              void* d_out, int out_size) {
    (void)in_sizes; (void)n_in; (void)out_size;
    const float* Q  = (const float*)d_in[0];
    const float* K  = (const float*)d_in[1];
    const float* V  = (const float*)d_in[2];
    const float* Wq = (const float*)d_in[3];
    const float* bq = (const float*)d_in[4];
    const float* Wk = (const float*)d_in[5];
    const float* bk = (const float*)d_in[6];
    const float* Wv = (const float*)d_in[7];
    const float* bv = (const float*)d_in[8];
    const float* Wo = (const float*)d_in[9];
    const float* bo = (const float*)d_in[10];

    __nv_bfloat16 *qh, *ql, *kh, *kl, *vh, *vl, *ah, *al;
    __nv_bfloat16 *aqh, *aql, *akh, *akl, *avh, *avl;
    __nv_bfloat16 *wqh, *wql, *wkh, *wkl, *wvh, *wvl, *woh, *wol;
    cudaGetSymbolAddress((void**)&qh, g_qh);   cudaGetSymbolAddress((void**)&ql, g_ql);
    cudaGetSymbolAddress((void**)&kh, g_kh);   cudaGetSymbolAddress((void**)&kl, g_kl);
    cudaGetSymbolAddress((void**)&vh, g_vh);   cudaGetSymbolAddress((void**)&vl, g_vl);
    cudaGetSymbolAddress((void**)&ah, g_ah);   cudaGetSymbolAddress((void**)&al, g_al);
    cudaGetSymbolAddress((void**)&aqh, g_aqh); cudaGetSymbolAddress((void**)&aql, g_aql);
    cudaGetSymbolAddress((void**)&akh, g_akh); cudaGetSymbolAddress((void**)&akl, g_akl);
    cudaGetSymbolAddress((void**)&avh, g_avh); cudaGetSymbolAddress((void**)&avl, g_avl);
    cudaGetSymbolAddress((void**)&wqh, g_wqh); cudaGetSymbolAddress((void**)&wql, g_wql);
    cudaGetSymbolAddress((void**)&wkh, g_wkh); cudaGetSymbolAddress((void**)&wkl, g_wkl);
    cudaGetSymbolAddress((void**)&wvh, g_wvh); cudaGetSymbolAddress((void**)&wvl, g_wvl);
    cudaGetSymbolAddress((void**)&woh, g_woh); cudaGetSymbolAddress((void**)&wol, g_wol);

    cudaFuncSetAttribute(gemm_qkv, cudaFuncAttributeMaxDynamicSharedMemorySize, GM_SMEM);
    cudaFuncSetAttribute(gemm_out, cudaFuncAttributeMaxDynamicSharedMemorySize, GM_SMEM);
    cudaFuncSetAttribute(flash_hmma, cudaFuncAttributeMaxDynamicSharedMemorySize, FA_SMEM);

    const int wblk = (DM * DM / 4) / 1024;     // 256
    const int ablk = (MTOT * DM / 4) / 1024;   // 2048

    // 1. split all 4 weights
    split_multi<<<dim3(wblk, 4), 256>>>(Wq, wqh, wql, Wk, wkh, wkl,
                                        Wv, wvh, wvl, Wo, woh, wol);
    // 2. split Q/K/V activations
    split_multi<<<dim3(ablk, 3), 256>>>(Q, aqh, aql, K, akh, akl,
                                        V, avh, avl, nullptr, nullptr, nullptr);
    // 3. batched QKV projections (Q pre-scaled by 0.125*log2(e))
    GemmJob jq = {aqh, aql, wqh, wql, bq, qh, ql, SCALE_LOG2};
    GemmJob jk = {akh, akl, wkh, wkl, bk, kh, kl, 1.0f};
    GemmJob jv = {avh, avl, wvh, wvl, bv, vh, vl, 1.0f};
    gemm_qkv<<<dim3(MTOT / 128, DM / 128, 3), 512, GM_SMEM>>>(jq, jk, jv);

    // 4. attention -> ah/al [B,S,DM]
    flash_hmma<<<dim3(SEQ / 128, BSZ * NH), 256, FA_SMEM>>>(qh, ql, kh, kl, vh, vl, ah, al);

    // 5. output projection -> d_out fp32
    gemm_out<<<dim3(MTOT / 128, DM / 128), 512, GM_SMEM>>>(ah, al, woh, wol, bo, (float*)d_out);
}